// round 3
// baseline (speedup 1.0000x reference)
#include <cuda_runtime.h>
#include <math.h>

// Problem constants
#define Nn   4096
#define Bb   32
#define Cc   16
#define Hh   64
#define Kc   3
#define P0   80           // C+H
#define P1   128          // H+H
#define NC0  (Bb*P0)      // 2560
#define NC1  (Bb*P1)      // 4096
#define KP0  (Kc*P0)      // 240
#define KP1  (Kc*P1)      // 384
#define GH   256          // 4*H
#define ROWS (Bb*Nn)      // 131072

// Scratch (allocation-free rule: __device__ globals)
__device__ float g_combT[(size_t)Nn * NC1];      // 67 MB  (reused both layers)
__device__ float g_supp [(size_t)ROWS * KP1];    // 201 MB
__device__ float g_gates[(size_t)ROWS * GH];     // 134 MB
__device__ float g_ht0  [(size_t)Bb * Nn * Hh];  // 33.5 MB

// ---------------------------------------------------------------------------
// TF32 tensor-core GEMM: C[M x Ncols] = A[M x Kd] * B[Kd x Ncols]
// BM=128, BN=128, BK=16, 256 threads (8 warps as 4x2, warp tile 32x64)
// MODE 0: supp epilogue  -> C[((b*Nn+row)*Kc + blockIdx.z)*P + p], col = b*P+p
// MODE 1: gates epilogue -> C[row*GH + col] + bias[col]
// ---------------------------------------------------------------------------
#define BM 128
#define BN 128
#define BK 16
#define LDAS 20    // A smem row stride (floats): conflict-free frag loads, 16B rows
#define LDBS 132   // B smem row stride (floats): <=2-way conflicts, 16B aligned

__device__ __forceinline__ unsigned f2tf(float f) {
    unsigned r;
    asm("cvt.rna.tf32.f32 %0, %1;" : "=r"(r) : "f"(f));
    return r;
}
__device__ __forceinline__ void cp16(void* smem, const void* gmem) {
    unsigned s = (unsigned)__cvta_generic_to_shared(smem);
    asm volatile("cp.async.cg.shared.global [%0], [%1], 16;" :: "r"(s), "l"(gmem));
}

template<int MODE>
__global__ void __launch_bounds__(256, 2)
gemm_tf32(const float* __restrict__ Ag, int lda,
          const float* __restrict__ Bg, int ldb,
          float* __restrict__ Cg, int Kd,
          int Pcols, const float* __restrict__ bias)
{
    __shared__ __align__(16) float As[2][BM * LDAS];
    __shared__ __align__(16) float Bs[2][BK * LDBS];

    const int tid = threadIdx.x;
    const int bm0 = blockIdx.y * BM;
    const int bn0 = blockIdx.x * BN;
    if (MODE == 0) Ag += (size_t)blockIdx.z * Nn * Nn;

    // cooperative load indices
    const int arow = tid >> 2;        // 0..63  (two passes: +0, +64)
    const int acol = (tid & 3) * 4;   // 0,4,8,12
    const int brow = tid >> 5;        // 0..7   (two passes: +0, +8)
    const int bcol = (tid & 31) * 4;  // 0..124

    const int warp = tid >> 5, lane = tid & 31;
    const int wm = warp >> 1, wn = warp & 1;
    const int lq = lane >> 2;   // 0..7
    const int lr = lane & 3;    // 0..3

    float acc[2][8][4];
    #pragma unroll
    for (int i = 0; i < 2; i++)
        #pragma unroll
        for (int j = 0; j < 8; j++)
            #pragma unroll
            for (int r = 0; r < 4; r++) acc[i][j][r] = 0.f;

    const int nK = Kd / BK;

    auto prefetch = [&](int buf, int kt) {
        const int k0 = kt * BK;
        const float* Ab = Ag + (size_t)bm0 * lda + k0;
        #pragma unroll
        for (int i = 0; i < 2; i++) {
            int r = arow + i * 64;
            cp16(&As[buf][r * LDAS + acol], Ab + (size_t)r * lda + acol);
        }
        const float* Bp = Bg + (size_t)k0 * ldb + bn0;
        #pragma unroll
        for (int i = 0; i < 2; i++) {
            int r = brow + i * 8;
            cp16(&Bs[buf][r * LDBS + bcol], Bp + (size_t)r * ldb + bcol);
        }
    };

    prefetch(0, 0);
    asm volatile("cp.async.commit_group;");

    for (int kt = 0; kt < nK; kt++) {
        const int buf = kt & 1;
        if (kt + 1 < nK) {
            prefetch(buf ^ 1, kt + 1);
            asm volatile("cp.async.commit_group;");
            asm volatile("cp.async.wait_group 1;");
        } else {
            asm volatile("cp.async.wait_group 0;");
        }
        __syncthreads();

        const float* As_ = As[buf];
        const float* Bs_ = Bs[buf];
        #pragma unroll
        for (int kk = 0; kk < 2; kk++) {
            unsigned afr[2][4];
            #pragma unroll
            for (int mi = 0; mi < 2; mi++) {
                const int r = wm * 32 + mi * 16 + lq;
                const int c = kk * 8 + lr;
                afr[mi][0] = f2tf(As_[r * LDAS + c]);
                afr[mi][1] = f2tf(As_[(r + 8) * LDAS + c]);
                afr[mi][2] = f2tf(As_[r * LDAS + c + 4]);
                afr[mi][3] = f2tf(As_[(r + 8) * LDAS + c + 4]);
            }
            unsigned bfr[8][2];
            #pragma unroll
            for (int j = 0; j < 8; j++) {
                const int kq = kk * 8 + lr;
                const int n = wn * 64 + j * 8 + lq;
                bfr[j][0] = f2tf(Bs_[kq * LDBS + n]);
                bfr[j][1] = f2tf(Bs_[(kq + 4) * LDBS + n]);
            }
            #pragma unroll
            for (int mi = 0; mi < 2; mi++)
                #pragma unroll
                for (int j = 0; j < 8; j++)
                    asm volatile(
                        "mma.sync.aligned.m16n8k8.row.col.f32.tf32.tf32.f32 "
                        "{%0,%1,%2,%3}, {%4,%5,%6,%7}, {%8,%9}, {%0,%1,%2,%3};"
                        : "+f"(acc[mi][j][0]), "+f"(acc[mi][j][1]),
                          "+f"(acc[mi][j][2]), "+f"(acc[mi][j][3])
                        : "r"(afr[mi][0]), "r"(afr[mi][1]),
                          "r"(afr[mi][2]), "r"(afr[mi][3]),
                          "r"(bfr[j][0]),  "r"(bfr[j][1]));
        }
        __syncthreads();
    }

    // Epilogue
    #pragma unroll
    for (int mi = 0; mi < 2; mi++) {
        #pragma unroll
        for (int j = 0; j < 8; j++) {
            #pragma unroll
            for (int r = 0; r < 4; r++) {
                const int row = bm0 + wm * 32 + mi * 16 + lq + ((r >= 2) ? 8 : 0);
                const int col = bn0 + wn * 64 + j * 8 + lr * 2 + (r & 1);
                const float v = acc[mi][j][r];
                if (MODE == 0) {
                    const int bi = col / Pcols;
                    const int p  = col - bi * Pcols;
                    Cg[(((size_t)bi * Nn + row) * Kc + blockIdx.z) * Pcols + p] = v;
                } else {
                    Cg[(size_t)row * GH + col] = v + bias[col];
                }
            }
        }
    }
}

// ---------------------------------------------------------------------------
// combT builders: combT[m][b*P + p]
// ---------------------------------------------------------------------------
__global__ void comb0_k(const float* __restrict__ x, const float* __restrict__ h0)
{
    const int idx = blockIdx.x * blockDim.x + threadIdx.x;
    if (idx >= Nn * NC0) return;
    const int col = idx % NC0;
    const int m   = idx / NC0;
    const int b   = col / P0;
    const int p   = col - b * P0;
    const float v = (p < Cc) ? x [((size_t)b * Nn + m) * Cc + p]
                             : h0[((size_t)b * Nn + m) * Hh + (p - Cc)];
    g_combT[(size_t)m * NC0 + col] = v;
}

__global__ void comb1_k(const float* __restrict__ h1)
{
    const int idx = blockIdx.x * blockDim.x + threadIdx.x;
    if (idx >= Nn * NC1) return;
    const int col = idx & (NC1 - 1);
    const int m   = idx >> 12;            // NC1 == 4096
    const int b   = col >> 7;             // P1 == 128
    const int p   = col & 127;
    const float v = (p < Hh) ? g_ht0[((size_t)b * Nn + m) * Hh + p]
                             : h1  [((size_t)b * Nn + m) * Hh + (p - Hh)];
    g_combT[(size_t)m * NC1 + col] = v;
}

// ---------------------------------------------------------------------------
// Fused LSTM elementwise: gates[row,0:64]=i, 64:128=f, 128:192=o, 192:256=g
// ---------------------------------------------------------------------------
__global__ void lstm_k(const float* __restrict__ gates, const float* __restrict__ cpre,
                       float* __restrict__ ho1, float* __restrict__ ho2,
                       float* __restrict__ co,  float* __restrict__ hscr)
{
    const int i = blockIdx.x * blockDim.x + threadIdx.x;
    if (i >= Bb * Nn * Hh) return;
    const int h   = i & (Hh - 1);
    const int row = i >> 6;
    const float* g = gates + (size_t)row * GH;
    const float gi = g[h], gf = g[h + 64], go = g[h + 128], gg = g[h + 192];
    const float si = 1.f / (1.f + expf(-gi));
    const float sf = 1.f / (1.f + expf(-gf));
    const float so = 1.f / (1.f + expf(-go));
    const float ct = sf * cpre[i] + si * tanhf(gg);
    const float ht = so * tanhf(ct);
    if (ho1)  ho1[i]  = ht;
    if (ho2)  ho2[i]  = ht;
    if (co)   co[i]   = ct;
    if (hscr) hscr[i] = ht;
}

// ---------------------------------------------------------------------------
extern "C" void kernel_launch(void* const* d_in, const int* in_sizes, int n_in,
                              void* d_out, int out_size)
{
    (void)in_sizes; (void)n_in; (void)out_size;
    const float* G  = (const float*)d_in[0];
    const float* xt = (const float*)d_in[1];
    const float* h0 = (const float*)d_in[2];
    const float* h1 = (const float*)d_in[3];
    const float* c0 = (const float*)d_in[4];
    const float* c1 = (const float*)d_in[5];
    const float* W0 = (const float*)d_in[6];
    const float* b0 = (const float*)d_in[7];
    const float* W1 = (const float*)d_in[8];
    const float* b1 = (const float*)d_in[9];
    float* out = (float*)d_out;

    float *combT, *supp, *gates, *ht0;
    cudaGetSymbolAddress((void**)&combT, g_combT);
    cudaGetSymbolAddress((void**)&supp,  g_supp);
    cudaGetSymbolAddress((void**)&gates, g_gates);
    cudaGetSymbolAddress((void**)&ht0,   g_ht0);

    const size_t S = (size_t)Bb * Nn * Hh;   // 8388608 elements per output slot

    // ---- layer 0 ----
    comb0_k<<<(Nn * NC0 + 255) / 256, 256>>>(xt, h0);

    {   // supp0[b,n,k,p] = G[k] @ combT   (3 hops via grid.z)
        dim3 grid(NC0 / BN, Nn / BM, Kc);   // 20 x 32 x 3
        gemm_tf32<0><<<grid, 256>>>(G, Nn, combT, NC0, supp, Nn, P0, nullptr);
    }
    {   // gates0 = supp0 @ W0 + b0
        dim3 grid(GH / BN, ROWS / BM, 1);   // 2 x 1024
        gemm_tf32<1><<<grid, 256>>>(supp, KP0, W0, GH, gates, KP0, 0, b0);
    }
    // h_t0 -> out slot 1 and scratch; c_t0 -> out slot 3
    lstm_k<<<(int)((S + 255) / 256), 256>>>(gates, c0, out + S, nullptr, out + 3 * S, ht0);

    // ---- layer 1 ----
    comb1_k<<<(Nn * NC1 + 255) / 256, 256>>>(h1);

    {
        dim3 grid(NC1 / BN, Nn / BM, Kc);   // 32 x 32 x 3
        gemm_tf32<0><<<grid, 256>>>(G, Nn, combT, NC1, supp, Nn, P1, nullptr);
    }
    {
        dim3 grid(GH / BN, ROWS / BM, 1);
        gemm_tf32<1><<<grid, 256>>>(supp, KP1, W1, GH, gates, KP1, 0, b1);
    }
    // h_t1 -> out slots 0 and 2; c_t1 -> out slot 4
    lstm_k<<<(int)((S + 255) / 256), 256>>>(gates, c1, out, out + 2 * S, out + 4 * S, nullptr);
}

// round 4
// speedup vs baseline: 1.0012x; 1.0012x over previous
#include <cuda_runtime.h>
#include <math.h>

// Problem constants
#define Nn   4096
#define Bb   32
#define Cc   16
#define Hh   64
#define Kc   3
#define P0   80           // C+H
#define P1   128          // H+H
#define NC0  (Bb*P0)      // 2560
#define NC1  (Bb*P1)      // 4096
#define KP0  (Kc*P0)      // 240
#define KP1  (Kc*P1)      // 384
#define GH   256          // 4*H
#define ROWS (Bb*Nn)      // 131072

// Scratch (allocation-free rule: __device__ globals)
__device__ float g_combT[(size_t)Nn * NC1];      // 67 MB  (reused both layers)
__device__ float g_supp [(size_t)ROWS * KP1];    // 201 MB
__device__ float g_gates[(size_t)ROWS * GH];     // 134 MB
__device__ float g_ht0  [(size_t)Bb * Nn * Hh];  // 33.5 MB

// ---------------------------------------------------------------------------
// TF32 tensor-core GEMM: C[M x Ncols] = A[M x Kd] * B[Kd x Ncols]
// BM=128, BN=128, BK=16, 256 threads (8 warps as 4x2, warp tile 32x64)
// MODE 0: supp epilogue  -> C[((b*Nn+row)*Kc + blockIdx.z)*P + p], col = b*P+p
// MODE 1: gates epilogue -> C[row*GH + col] + bias[col]
// ---------------------------------------------------------------------------
#define BM 128
#define BN 128
#define BK 16
#define LDAS 20    // A smem row stride (floats): conflict-free frag loads, 16B rows
#define LDBS 132   // B smem row stride (floats): <=2-way conflicts, 16B aligned

__device__ __forceinline__ unsigned f2tf(float f) {
    unsigned r;
    asm("cvt.rna.tf32.f32 %0, %1;" : "=r"(r) : "f"(f));
    return r;
}
__device__ __forceinline__ void cp16(void* smem, const void* gmem) {
    unsigned s = (unsigned)__cvta_generic_to_shared(smem);
    asm volatile("cp.async.cg.shared.global [%0], [%1], 16;" :: "r"(s), "l"(gmem));
}

template<int MODE>
__global__ void __launch_bounds__(256, 2)
gemm_tf32(const float* __restrict__ Ag, int lda,
          const float* __restrict__ Bg, int ldb,
          float* __restrict__ Cg, int Kd,
          int Pcols, const float* __restrict__ bias)
{
    __shared__ __align__(16) float As[2][BM * LDAS];
    __shared__ __align__(16) float Bs[2][BK * LDBS];

    const int tid = threadIdx.x;
    const int bm0 = blockIdx.y * BM;
    const int bn0 = blockIdx.x * BN;
    if (MODE == 0) Ag += (size_t)blockIdx.z * Nn * Nn;

    // cooperative load indices
    const int arow = tid >> 2;        // 0..63  (two passes: +0, +64)
    const int acol = (tid & 3) * 4;   // 0,4,8,12
    const int brow = tid >> 5;        // 0..7   (two passes: +0, +8)
    const int bcol = (tid & 31) * 4;  // 0..124

    const int warp = tid >> 5, lane = tid & 31;
    const int wm = warp >> 1, wn = warp & 1;
    const int lq = lane >> 2;   // 0..7
    const int lr = lane & 3;    // 0..3

    float acc[2][8][4];
    #pragma unroll
    for (int i = 0; i < 2; i++)
        #pragma unroll
        for (int j = 0; j < 8; j++)
            #pragma unroll
            for (int r = 0; r < 4; r++) acc[i][j][r] = 0.f;

    const int nK = Kd / BK;

    auto prefetch = [&](int buf, int kt) {
        const int k0 = kt * BK;
        const float* Ab = Ag + (size_t)bm0 * lda + k0;
        #pragma unroll
        for (int i = 0; i < 2; i++) {
            int r = arow + i * 64;
            cp16(&As[buf][r * LDAS + acol], Ab + (size_t)r * lda + acol);
        }
        const float* Bp = Bg + (size_t)k0 * ldb + bn0;
        #pragma unroll
        for (int i = 0; i < 2; i++) {
            int r = brow + i * 8;
            cp16(&Bs[buf][r * LDBS + bcol], Bp + (size_t)r * ldb + bcol);
        }
    };

    prefetch(0, 0);
    asm volatile("cp.async.commit_group;");

    for (int kt = 0; kt < nK; kt++) {
        const int buf = kt & 1;
        if (kt + 1 < nK) {
            prefetch(buf ^ 1, kt + 1);
            asm volatile("cp.async.commit_group;");
            asm volatile("cp.async.wait_group 1;");
        } else {
            asm volatile("cp.async.wait_group 0;");
        }
        __syncthreads();

        const float* As_ = As[buf];
        const float* Bs_ = Bs[buf];
        #pragma unroll
        for (int kk = 0; kk < 2; kk++) {
            unsigned afr[2][4];
            #pragma unroll
            for (int mi = 0; mi < 2; mi++) {
                const int r = wm * 32 + mi * 16 + lq;
                const int c = kk * 8 + lr;
                afr[mi][0] = f2tf(As_[r * LDAS + c]);
                afr[mi][1] = f2tf(As_[(r + 8) * LDAS + c]);
                afr[mi][2] = f2tf(As_[r * LDAS + c + 4]);
                afr[mi][3] = f2tf(As_[(r + 8) * LDAS + c + 4]);
            }
            unsigned bfr[8][2];
            #pragma unroll
            for (int j = 0; j < 8; j++) {
                const int kq = kk * 8 + lr;
                const int n = wn * 64 + j * 8 + lq;
                bfr[j][0] = f2tf(Bs_[kq * LDBS + n]);
                bfr[j][1] = f2tf(Bs_[(kq + 4) * LDBS + n]);
            }
            #pragma unroll
            for (int mi = 0; mi < 2; mi++)
                #pragma unroll
                for (int j = 0; j < 8; j++)
                    asm volatile(
                        "mma.sync.aligned.m16n8k8.row.col.f32.tf32.tf32.f32 "
                        "{%0,%1,%2,%3}, {%4,%5,%6,%7}, {%8,%9}, {%0,%1,%2,%3};"
                        : "+f"(acc[mi][j][0]), "+f"(acc[mi][j][1]),
                          "+f"(acc[mi][j][2]), "+f"(acc[mi][j][3])
                        : "r"(afr[mi][0]), "r"(afr[mi][1]),
                          "r"(afr[mi][2]), "r"(afr[mi][3]),
                          "r"(bfr[j][0]),  "r"(bfr[j][1]));
        }
        __syncthreads();
    }

    // Epilogue
    #pragma unroll
    for (int mi = 0; mi < 2; mi++) {
        #pragma unroll
        for (int j = 0; j < 8; j++) {
            #pragma unroll
            for (int r = 0; r < 4; r++) {
                const int row = bm0 + wm * 32 + mi * 16 + lq + ((r >= 2) ? 8 : 0);
                const int col = bn0 + wn * 64 + j * 8 + lr * 2 + (r & 1);
                const float v = acc[mi][j][r];
                if (MODE == 0) {
                    const int bi = col / Pcols;
                    const int p  = col - bi * Pcols;
                    Cg[(((size_t)bi * Nn + row) * Kc + blockIdx.z) * Pcols + p] = v;
                } else {
                    Cg[(size_t)row * GH + col] = v + bias[col];
                }
            }
        }
    }
}

// ---------------------------------------------------------------------------
// combT builders: combT[m][b*P + p]
// ---------------------------------------------------------------------------
__global__ void comb0_k(const float* __restrict__ x, const float* __restrict__ h0)
{
    const int idx = blockIdx.x * blockDim.x + threadIdx.x;
    if (idx >= Nn * NC0) return;
    const int col = idx % NC0;
    const int m   = idx / NC0;
    const int b   = col / P0;
    const int p   = col - b * P0;
    const float v = (p < Cc) ? x [((size_t)b * Nn + m) * Cc + p]
                             : h0[((size_t)b * Nn + m) * Hh + (p - Cc)];
    g_combT[(size_t)m * NC0 + col] = v;
}

__global__ void comb1_k(const float* __restrict__ h1)
{
    const int idx = blockIdx.x * blockDim.x + threadIdx.x;
    if (idx >= Nn * NC1) return;
    const int col = idx & (NC1 - 1);
    const int m   = idx >> 12;            // NC1 == 4096
    const int b   = col >> 7;             // P1 == 128
    const int p   = col & 127;
    const float v = (p < Hh) ? g_ht0[((size_t)b * Nn + m) * Hh + p]
                             : h1  [((size_t)b * Nn + m) * Hh + (p - Hh)];
    g_combT[(size_t)m * NC1 + col] = v;
}

// ---------------------------------------------------------------------------
// Fused LSTM elementwise: gates[row,0:64]=i, 64:128=f, 128:192=o, 192:256=g
// ---------------------------------------------------------------------------
__global__ void lstm_k(const float* __restrict__ gates, const float* __restrict__ cpre,
                       float* __restrict__ ho1, float* __restrict__ ho2,
                       float* __restrict__ co,  float* __restrict__ hscr)
{
    const int i = blockIdx.x * blockDim.x + threadIdx.x;
    if (i >= Bb * Nn * Hh) return;
    const int h   = i & (Hh - 1);
    const int row = i >> 6;
    const float* g = gates + (size_t)row * GH;
    const float gi = g[h], gf = g[h + 64], go = g[h + 128], gg = g[h + 192];
    const float si = 1.f / (1.f + expf(-gi));
    const float sf = 1.f / (1.f + expf(-gf));
    const float so = 1.f / (1.f + expf(-go));
    const float ct = sf * cpre[i] + si * tanhf(gg);
    const float ht = so * tanhf(ct);
    if (ho1)  ho1[i]  = ht;
    if (ho2)  ho2[i]  = ht;
    if (co)   co[i]   = ct;
    if (hscr) hscr[i] = ht;
}

// ---------------------------------------------------------------------------
extern "C" void kernel_launch(void* const* d_in, const int* in_sizes, int n_in,
                              void* d_out, int out_size)
{
    (void)in_sizes; (void)n_in; (void)out_size;
    const float* G  = (const float*)d_in[0];
    const float* xt = (const float*)d_in[1];
    const float* h0 = (const float*)d_in[2];
    const float* h1 = (const float*)d_in[3];
    const float* c0 = (const float*)d_in[4];
    const float* c1 = (const float*)d_in[5];
    const float* W0 = (const float*)d_in[6];
    const float* b0 = (const float*)d_in[7];
    const float* W1 = (const float*)d_in[8];
    const float* b1 = (const float*)d_in[9];
    float* out = (float*)d_out;

    float *combT, *supp, *gates, *ht0;
    cudaGetSymbolAddress((void**)&combT, g_combT);
    cudaGetSymbolAddress((void**)&supp,  g_supp);
    cudaGetSymbolAddress((void**)&gates, g_gates);
    cudaGetSymbolAddress((void**)&ht0,   g_ht0);

    const size_t S = (size_t)Bb * Nn * Hh;   // 8388608 elements per output slot

    // ---- layer 0 ----
    comb0_k<<<(Nn * NC0 + 255) / 256, 256>>>(xt, h0);

    {   // supp0[b,n,k,p] = G[k] @ combT   (3 hops via grid.z)
        dim3 grid(NC0 / BN, Nn / BM, Kc);   // 20 x 32 x 3
        gemm_tf32<0><<<grid, 256>>>(G, Nn, combT, NC0, supp, Nn, P0, nullptr);
    }
    {   // gates0 = supp0 @ W0 + b0
        dim3 grid(GH / BN, ROWS / BM, 1);   // 2 x 1024
        gemm_tf32<1><<<grid, 256>>>(supp, KP0, W0, GH, gates, KP0, 0, b0);
    }
    // h_t0 -> out slot 1 and scratch; c_t0 -> out slot 3
    lstm_k<<<(int)((S + 255) / 256), 256>>>(gates, c0, out + S, nullptr, out + 3 * S, ht0);

    // ---- layer 1 ----
    comb1_k<<<(Nn * NC1 + 255) / 256, 256>>>(h1);

    {
        dim3 grid(NC1 / BN, Nn / BM, Kc);   // 32 x 32 x 3
        gemm_tf32<0><<<grid, 256>>>(G, Nn, combT, NC1, supp, Nn, P1, nullptr);
    }
    {
        dim3 grid(GH / BN, ROWS / BM, 1);
        gemm_tf32<1><<<grid, 256>>>(supp, KP1, W1, GH, gates, KP1, 0, b1);
    }
    // h_t1 -> out slots 0 and 2; c_t1 -> out slot 4
    lstm_k<<<(int)((S + 255) / 256), 256>>>(gates, c1, out, out + 2 * S, out + 4 * S, nullptr);
}

// round 9
// speedup vs baseline: 1.1386x; 1.1372x over previous
#include <cuda_runtime.h>
#include <math.h>
#include <stdint.h>

// ---------------- problem constants ----------------
#define Nn    4096
#define Bb    32
#define Cc    16
#define Hh    64
#define Kc    3
#define P0    80
#define P1    128
#define NC0   (Bb*P0)     // 2560
#define NC1   (Bb*P1)     // 4096
#define KP0   (Kc*P0)     // 240
#define KP1   (Kc*P1)     // 384
#define GH    256
#define ROWS  (Bb*Nn)     // 131072

// ---------------- GEMM tiling ----------------
#define BM   128
#define BN   256
#define NSTG 4
#define ASTG 8192                  // 128x16 fp32 packed A
#define BSTG 16384                 // 16x256 fp32 packed B
#define STG  (ASTG + BSTG)         // 24576
#define SMEM_MAIN (NSTG * STG)     // 98304

// ---------------- scratch (__device__ globals) ----------------
// packed A for supp GEMM: [z][mt(32)][kt(256)] blocks of 512 float4
__device__ float4 g_GP   [(size_t)Kc * 32 * 256 * 512];        // 201 MB
// packed B (comb): [nt(<=16)][kt(256)] blocks of 1024 float4
__device__ float4 g_combP[(size_t)16 * 256 * 1024];            // 67 MB
// packed A for gates GEMM: [mt(1024)][kt(<=24)] blocks of 512 float4
__device__ float4 g_suppP[(size_t)1024 * 24 * 512];            // 201 MB
// packed B (W^T-ish): [kt(<=24)] blocks of 1024 float4
__device__ float4 g_WtP  [(size_t)24 * 1024];
__device__ float  g_ht0  [(size_t)ROWS * Hh];                  // 33.5 MB

// ---------------- helpers ----------------
__device__ __forceinline__ float rna(float f) {
    unsigned u; asm("cvt.rna.tf32.f32 %0, %1;" : "=r"(u) : "f"(f));
    return __uint_as_float(u);
}
__device__ __forceinline__ float sigm(float x) { return 1.f / (1.f + expf(-x)); }

__device__ __forceinline__ void cp16(void* s, const void* g) {
    uint32_t a;
    asm("{ .reg .u64 t; cvta.to.shared.u64 t, %1; cvt.u32.u64 %0, t; }" : "=r"(a) : "l"(s));
    asm volatile("cp.async.cg.shared.global [%0], [%1], 16;" :: "r"(a), "l"(g));
}
#define CP_COMMIT() asm volatile("cp.async.commit_group;")
#define CP_WAIT3()  asm volatile("cp.async.wait_group 3;")

#define MMA(accq, af, b0, b1) \
    asm volatile("mma.sync.aligned.m16n8k8.row.col.f32.tf32.tf32.f32 " \
        "{%0,%1,%2,%3}, {%4,%5,%6,%7}, {%8,%9}, {%0,%1,%2,%3};" \
        : "+f"((accq)[0]), "+f"((accq)[1]), "+f"((accq)[2]), "+f"((accq)[3]) \
        : "r"((af).x), "r"((af).y), "r"((af).z), "r"((af).w), "r"(b0), "r"(b1))

// ---------------------------------------------------------------------------
// Packed-fragment tf32 GEMM. C[BMxBN] per CTA, K in tiles of 16.
//  A packed per (Atile, kt): [kk(2)][g16(8)][lane(32)] float4 = (r,c / r+8,c / r,c+4 / r+8,c+4)
//  B packed per (Btile, kt): [kk(2)][jp(16)][lane(32)] float4 = (B[c][n], B[c+4][n], B[c][n+8], B[c+4][n+8])
// 8 warps (2x4), warp tile 64x64. Epilogues staged through smem.
// MODE 0: write supp in packed-A layout for the gates GEMM (+rna round).
// MODE 1: fused bias + LSTM.
// ---------------------------------------------------------------------------
template<int MODE, int PC>
__global__ void __launch_bounds__(256, 1)
gemm_pk(const float4* __restrict__ Ap, const float4* __restrict__ Bp,
        int nkt, float4* __restrict__ outP, int nktOut,
        const float* __restrict__ bias, const float* __restrict__ cpre,
        float* __restrict__ ho1, float* __restrict__ ho2,
        float* __restrict__ co,  float* __restrict__ hscr)
{
    extern __shared__ char smem[];
    const int tid  = threadIdx.x;
    const int wid  = tid >> 5, lane = tid & 31;
    const int wm   = wid >> 2, wn = wid & 3;
    const int bm0  = blockIdx.y * BM;
    const int bn0  = blockIdx.x * BN;
    const int z    = blockIdx.z;

    const float4* Abase = Ap + ((size_t)z * gridDim.y + blockIdx.y) * nkt * 512;
    const float4* Bbase = Bp + (size_t)blockIdx.x * nkt * 1024;

    float acc[4][8][4];
    #pragma unroll
    for (int ai = 0; ai < 4; ai++)
        #pragma unroll
        for (int bj = 0; bj < 8; bj++)
            #pragma unroll
            for (int cq = 0; cq < 4; cq++) acc[ai][bj][cq] = 0.f;

    auto pf = [&](int s, int kt) {
        char* sA = smem + s * STG;
        char* sB = sA + ASTG;
        const float4* ag = Abase + (size_t)kt * 512;
        const float4* bg = Bbase + (size_t)kt * 1024;
        cp16(sA + tid * 16,          ag + tid);
        cp16(sA + (tid + 256) * 16,  ag + tid + 256);
        #pragma unroll
        for (int i = 0; i < 4; i++)
            cp16(sB + (tid + i * 256) * 16, bg + tid + i * 256);
    };

    pf(0, 0); CP_COMMIT();
    pf(1, 1); CP_COMMIT();
    pf(2, 2); CP_COMMIT();

    for (int kt = 0; kt < nkt; kt++) {
        if (kt + 3 < nkt) pf((kt + 3) & 3, kt + 3);
        CP_COMMIT();
        CP_WAIT3();
        __syncthreads();

        const int s = kt & 3;
        const uint4* sA = (const uint4*)(smem + s * STG);
        const uint4* sB = (const uint4*)(smem + s * STG + ASTG);
        #pragma unroll
        for (int kk = 0; kk < 2; kk++) {
            uint4 af[4], bf[4];
            #pragma unroll
            for (int mi = 0; mi < 4; mi++)
                af[mi] = sA[(kk * 8 + wm * 4 + mi) * 32 + lane];
            #pragma unroll
            for (int jp = 0; jp < 4; jp++)
                bf[jp] = sB[(kk * 16 + wn * 4 + jp) * 32 + lane];
            #pragma unroll
            for (int mi = 0; mi < 4; mi++)
                #pragma unroll
                for (int jp = 0; jp < 4; jp++) {
                    MMA(acc[mi][jp * 2],     af[mi], bf[jp].x, bf[jp].y);
                    MMA(acc[mi][jp * 2 + 1], af[mi], bf[jp].z, bf[jp].w);
                }
        }
        __syncthreads();
    }

    // ---------------- epilogue (staged per 64-row half) ----------------
    const int lq = lane >> 2, lr = lane & 3;
    float* sC = (float*)smem;                 // [64][260]

    for (int h = 0; h < 2; h++) {
        if (wm == h) {
            #pragma unroll
            for (int mi = 0; mi < 4; mi++)
                #pragma unroll
                for (int j = 0; j < 8; j++) {
                    const int r0 = mi * 16 + lq;
                    const int c0 = wn * 64 + j * 8 + lr * 2;
                    sC[r0 * 260 + c0]           = acc[mi][j][0];
                    sC[r0 * 260 + c0 + 1]       = acc[mi][j][1];
                    sC[(r0 + 8) * 260 + c0]     = acc[mi][j][2];
                    sC[(r0 + 8) * 260 + c0 + 1] = acc[mi][j][3];
                }
        }
        __syncthreads();

        if constexpr (MODE == 0) {
            // emit packed-A float4s for the gates GEMM
            #pragma unroll 4
            for (int it = 0; it < 16; it++) {
                const int idx = it * 256 + tid;        // 0..4095
                const int cp  = idx & 127;             // col-pair id
                const int rp  = idx >> 7;              // 0..31 row-pair id
                const int g8  = cp >> 2, lr2 = cp & 3;
                const int lc0 = g8 * 8 + lr2;
                const int g16l = rp >> 3, lq2 = rp & 7;
                const int rl0 = g16l * 16 + lq2;       // local row in half
                const float v00 = rna(sC[rl0 * 260 + lc0]);
                const float v10 = rna(sC[(rl0 + 8) * 260 + lc0]);
                const float v01 = rna(sC[rl0 * 260 + lc0 + 4]);
                const float v11 = rna(sC[(rl0 + 8) * 260 + lc0 + 4]);
                const int gc   = bn0 + lc0;
                const int bi   = gc / PC;
                const int p    = gc - bi * PC;
                const int kidx = z * PC + p;
                const int g16  = (h * 64 + rl0) >> 4;  // global 16-row group
                const int mt   = bi * (Nn / 128) + (bm0 >> 7);
                const int kt2  = kidx >> 4;
                const int kk2  = (kidx >> 3) & 1;
                const int lane2 = lq2 * 4 + lr2;
                const size_t f4i =
                    (((size_t)mt * nktOut + kt2) * 16 + (kk2 * 8 + g16)) * 32 + lane2;
                outP[f4i] = make_float4(v00, v10, v01, v11);
            }
        } else {
            // fused bias + LSTM; cols 0..63=i, 64..127=f, 128..191=o, 192..255=g
            #pragma unroll 4
            for (int it = 0; it < 16; it++) {
                const int idx  = it * 256 + tid;       // 0..4095
                const int row  = idx >> 6;             // 0..63
                const int hc   = idx & 63;
                const float gi = sC[row * 260 + hc]        + __ldg(bias + hc);
                const float gf = sC[row * 260 + 64 + hc]   + __ldg(bias + 64 + hc);
                const float go = sC[row * 260 + 128 + hc]  + __ldg(bias + 128 + hc);
                const float gg = sC[row * 260 + 192 + hc]  + __ldg(bias + 192 + hc);
                const size_t m  = (size_t)bm0 + h * 64 + row;
                const size_t ix = m * Hh + hc;
                const float ct = sigm(gf) * cpre[ix] + sigm(gi) * tanhf(gg);
                const float ht = sigm(go) * tanhf(ct);
                ho1[ix] = ht;
                if (ho2)  ho2[ix]  = ht;
                co[ix] = ct;
                if (hscr) hscr[ix] = ht;
            }
        }
        __syncthreads();
    }
}

// ---------------------------------------------------------------------------
// prep/pack kernels (all write tf32-rounded values)
// ---------------------------------------------------------------------------
// G -> packed A: idx = [z][mt(5b)][kt(8b)][blk(4b)][lane(5b)]
__global__ void packG_k(const float* __restrict__ G)
{
    const int idx = blockIdx.x * blockDim.x + threadIdx.x;
    if (idx >= Kc * 32 * 256 * 16 * 32) return;
    const int lane = idx & 31;
    const int blk  = (idx >> 5) & 15;
    const int kt   = (idx >> 9) & 255;
    const int mt   = (idx >> 17) & 31;
    const int z    = idx >> 22;
    const int kk = blk >> 3, g16 = blk & 7;
    const int lq = lane >> 2, lr = lane & 3;
    const int r = mt * 128 + g16 * 16 + lq;
    const int c = kt * 16 + kk * 8 + lr;
    const float* Gz = G + (size_t)z * Nn * Nn;
    g_GP[idx] = make_float4(
        rna(Gz[(size_t)r * Nn + c]),       rna(Gz[(size_t)(r + 8) * Nn + c]),
        rna(Gz[(size_t)r * Nn + c + 4]),   rna(Gz[(size_t)(r + 8) * Nn + c + 4]));
}

// comb value fetchers
__device__ __forceinline__ float comb0_val(const float* x, const float* h0, int m, int col) {
    const int b = col / P0, p = col - b * P0;
    return (p < Cc) ? x[((size_t)b * Nn + m) * Cc + p]
                    : h0[((size_t)b * Nn + m) * Hh + (p - Cc)];
}
__device__ __forceinline__ float comb1_val(const float* h1, int m, int col) {
    const int b = col >> 7, p = col & 127;
    return (p < Hh) ? g_ht0[((size_t)b * Nn + m) * Hh + p]
                    : h1[((size_t)b * Nn + m) * Hh + (p - Hh)];
}

// comb -> packed B: idx = [nt][kt(8b)][blk(5b)][lane(5b)]
__global__ void packC0_k(const float* __restrict__ x, const float* __restrict__ h0, int total)
{
    const int idx = blockIdx.x * blockDim.x + threadIdx.x;
    if (idx >= total) return;
    const int lane = idx & 31;
    const int blk  = (idx >> 5) & 31;
    const int kt   = (idx >> 10) & 255;
    const int nt   = idx >> 18;
    const int kk = blk >> 4, jp = blk & 15;
    const int lq = lane >> 2, lr = lane & 3;
    const int m0 = kt * 16 + kk * 8 + lr;
    const int c0 = nt * 256 + jp * 16 + lq;
    g_combP[idx] = make_float4(
        rna(comb0_val(x, h0, m0, c0)),     rna(comb0_val(x, h0, m0 + 4, c0)),
        rna(comb0_val(x, h0, m0, c0 + 8)), rna(comb0_val(x, h0, m0 + 4, c0 + 8)));
}
__global__ void packC1_k(const float* __restrict__ h1, int total)
{
    const int idx = blockIdx.x * blockDim.x + threadIdx.x;
    if (idx >= total) return;
    const int lane = idx & 31;
    const int blk  = (idx >> 5) & 31;
    const int kt   = (idx >> 10) & 255;
    const int nt   = idx >> 18;
    const int kk = blk >> 4, jp = blk & 15;
    const int lq = lane >> 2, lr = lane & 3;
    const int m0 = kt * 16 + kk * 8 + lr;
    const int c0 = nt * 256 + jp * 16 + lq;
    g_combP[idx] = make_float4(
        rna(comb1_val(h1, m0, c0)),     rna(comb1_val(h1, m0 + 4, c0)),
        rna(comb1_val(h1, m0, c0 + 8)), rna(comb1_val(h1, m0 + 4, c0 + 8)));
}

// W -> packed B: idx = [kt][blk(5b)][lane(5b)];  W is [KP][256] row-major
__global__ void packW_k(const float* __restrict__ W, int total)
{
    const int idx = blockIdx.x * blockDim.x + threadIdx.x;
    if (idx >= total) return;
    const int lane = idx & 31;
    const int blk  = (idx >> 5) & 31;
    const int kt   = idx >> 10;
    const int kk = blk >> 4, jp = blk & 15;
    const int lq = lane >> 2, lr = lane & 3;
    const int k0 = kt * 16 + kk * 8 + lr;
    const int g0 = jp * 16 + lq;
    g_WtP[idx] = make_float4(
        rna(W[(size_t)k0 * GH + g0]),       rna(W[(size_t)(k0 + 4) * GH + g0]),
        rna(W[(size_t)k0 * GH + g0 + 8]),   rna(W[(size_t)(k0 + 4) * GH + g0 + 8]));
}

// ---------------------------------------------------------------------------
extern "C" void kernel_launch(void* const* d_in, const int* in_sizes, int n_in,
                              void* d_out, int out_size)
{
    (void)in_sizes; (void)n_in; (void)out_size;
    const float* G  = (const float*)d_in[0];
    const float* xt = (const float*)d_in[1];
    const float* h0 = (const float*)d_in[2];
    const float* h1 = (const float*)d_in[3];
    const float* c0 = (const float*)d_in[4];
    const float* c1 = (const float*)d_in[5];
    const float* W0 = (const float*)d_in[6];
    const float* b0 = (const float*)d_in[7];
    const float* W1 = (const float*)d_in[8];
    const float* b1 = (const float*)d_in[9];
    float* out = (float*)d_out;

    float4 *GP, *combP, *suppP, *WtP;
    float  *ht0;
    cudaGetSymbolAddress((void**)&GP,    g_GP);
    cudaGetSymbolAddress((void**)&combP, g_combP);
    cudaGetSymbolAddress((void**)&suppP, g_suppP);
    cudaGetSymbolAddress((void**)&WtP,   g_WtP);
    cudaGetSymbolAddress((void**)&ht0,   g_ht0);

    cudaFuncSetAttribute(gemm_pk<0, P0>, cudaFuncAttributeMaxDynamicSharedMemorySize, SMEM_MAIN);
    cudaFuncSetAttribute(gemm_pk<0, P1>, cudaFuncAttributeMaxDynamicSharedMemorySize, SMEM_MAIN);
    cudaFuncSetAttribute(gemm_pk<1, P0>, cudaFuncAttributeMaxDynamicSharedMemorySize, SMEM_MAIN);

    const size_t S = (size_t)ROWS * Hh;   // 8388608 per output slot
    const int nktG  = Nn / 16;            // 256
    const int nkt0  = KP0 / 16;           // 15
    const int nkt1  = KP1 / 16;           // 24

    // pack G (both layers use it)
    packG_k<<<(Kc * 32 * 256 * 16 * 32) / 256, 256>>>(G);

    // ---- layer 0 ----
    {
        const int tot = (NC0 / 256) * 256 * 32 * 32;   // nt=10, kt=256, 1024 f4/blk
        packC0_k<<<(tot + 255) / 256, 256>>>(xt, h0, tot);
    }
    gemm_pk<0, P0><<<dim3(NC0 / BN, Nn / BM, Kc), 256, SMEM_MAIN>>>(
        GP, combP, nktG, suppP, nkt0,
        nullptr, nullptr, nullptr, nullptr, nullptr, nullptr);
    {
        const int tot = nkt0 * 1024;
        packW_k<<<(tot + 255) / 256, 256>>>(W0, tot);
    }
    gemm_pk<1, P0><<<dim3(1, ROWS / BM, 1), 256, SMEM_MAIN>>>(
        suppP, WtP, nkt0, nullptr, 0,
        b0, c0, out + S, nullptr, out + 3 * S, ht0);

    // ---- layer 1 ----
    {
        const int tot = (NC1 / 256) * 256 * 32 * 32;   // nt=16
        packC1_k<<<(tot + 255) / 256, 256>>>(h1, tot);
    }
    gemm_pk<0, P1><<<dim3(NC1 / BN, Nn / BM, Kc), 256, SMEM_MAIN>>>(
        GP, combP, nktG, suppP, nkt1,
        nullptr, nullptr, nullptr, nullptr, nullptr, nullptr);
    {
        const int tot = nkt1 * 1024;
        packW_k<<<(tot + 255) / 256, 256>>>(W1, tot);
    }
    gemm_pk<1, P0><<<dim3(1, ROWS / BM, 1), 256, SMEM_MAIN>>>(
        suppP, WtP, nkt1, nullptr, 0,
        b1, c1, out, out + 2 * S, out + 4 * S, nullptr);
}

// round 10
// speedup vs baseline: 1.3631x; 1.1971x over previous
#include <cuda_runtime.h>
#include <math.h>
#include <stdint.h>

// ---------------- problem constants ----------------
#define Nn    4096
#define Bb    32
#define Cc    16
#define Hh    64
#define Kc    3
#define P0    80
#define P1    128
#define NC0   (Bb*P0)     // 2560
#define NC1   (Bb*P1)     // 4096
#define KP0   (Kc*P0)     // 240
#define KP1   (Kc*P1)     // 384
#define GH    256
#define ROWS  (Bb*Nn)     // 131072

// ---------------- GEMM tiling ----------------
#define BM   128
#define BN   256
#define NSTG 3
#define ASTG 16384                 // 128x32 fp32 packed A
#define BSTG 32768                 // 32x256 fp32 packed B
#define STG  (ASTG + BSTG)         // 49152
#define SMEM_MAIN (NSTG * STG)     // 147456

// ---------------- scratch (__device__ globals) ----------------
// packed A for supp GEMM: [z][mt(32)][kt16(256)] blocks of 512 float4
__device__ float4 g_GP   [(size_t)Kc * 32 * 256 * 512];        // 201 MB
// packed B (comb): [nt(<=16)][kt16(256)] blocks of 1024 float4
__device__ float4 g_combP[(size_t)16 * 256 * 1024];            // 67 MB
// packed A for gates GEMM: [mt(1024)][kt16(<=24)] blocks of 512 float4
__device__ float4 g_suppP[(size_t)1024 * 24 * 512];            // 201 MB
// packed B (W^T-ish): [kt16(<=24)] blocks of 1024 float4
__device__ float4 g_WtP  [(size_t)24 * 1024];
__device__ float  g_ht0  [(size_t)ROWS * Hh];                  // 33.5 MB

// ---------------- helpers ----------------
__device__ __forceinline__ float rna(float f) {
    unsigned u; asm("cvt.rna.tf32.f32 %0, %1;" : "=r"(u) : "f"(f));
    return __uint_as_float(u);
}
__device__ __forceinline__ float sigm(float x) { return 1.f / (1.f + expf(-x)); }

__device__ __forceinline__ void cp16(void* s, const void* g) {
    uint32_t a;
    asm("{ .reg .u64 t; cvta.to.shared.u64 t, %1; cvt.u32.u64 %0, t; }" : "=r"(a) : "l"(s));
    asm volatile("cp.async.cg.shared.global [%0], [%1], 16;" :: "r"(a), "l"(g));
}
#define CP_COMMIT() asm volatile("cp.async.commit_group;")
#define CP_WAIT1()  asm volatile("cp.async.wait_group 1;")

#define MMA(accq, af, b0, b1) \
    asm volatile("mma.sync.aligned.m16n8k8.row.col.f32.tf32.tf32.f32 " \
        "{%0,%1,%2,%3}, {%4,%5,%6,%7}, {%8,%9}, {%0,%1,%2,%3};" \
        : "+f"((accq)[0]), "+f"((accq)[1]), "+f"((accq)[2]), "+f"((accq)[3]) \
        : "r"((af).x), "r"((af).y), "r"((af).z), "r"((af).w), "r"(b0), "r"(b1))

// ---------------------------------------------------------------------------
// Packed-fragment tf32 GEMM. C[BMxBN] per CTA, K consumed in 32-wide tiles
// (two consecutive 16-K packed blocks). 8 warps (2x4), warp tile 64x64.
// Single __syncthreads per iteration; 3-stage cp.async ring, 2 stages in flight.
//  A packed per (Atile, kt16): [kk(2)][g16(8)][lane(32)] float4
//  B packed per (Btile, kt16): [kk(2)][jp(16)][lane(32)] float4
// MODE 0: write supp in packed-A layout for the gates GEMM (+rna round).
// MODE 1: fused bias + LSTM.
// nkt is in 32-K tiles; nktOut (MODE 0) is in 16-K blocks.
// ---------------------------------------------------------------------------
template<int MODE, int PC>
__global__ void __launch_bounds__(256, 1)
gemm_pk(const float4* __restrict__ Ap, const float4* __restrict__ Bp,
        int nkt, float4* __restrict__ outP, int nktOut,
        const float* __restrict__ bias, const float* __restrict__ cpre,
        float* __restrict__ ho1, float* __restrict__ ho2,
        float* __restrict__ co,  float* __restrict__ hscr)
{
    extern __shared__ char smem[];
    const int tid  = threadIdx.x;
    const int wid  = tid >> 5, lane = tid & 31;
    const int wm   = wid >> 2, wn = wid & 3;
    const int bm0  = blockIdx.y * BM;
    const int bn0  = blockIdx.x * BN;
    const int z    = blockIdx.z;

    // A/B bases: k16-block granular layouts; one 32-K tile = 2 consecutive blocks
    const float4* Abase = Ap + ((size_t)z * gridDim.y + blockIdx.y) * (2 * nkt) * 512;
    const float4* Bbase = Bp + (size_t)blockIdx.x * (2 * nkt) * 1024;

    float acc[4][8][4];
    #pragma unroll
    for (int ai = 0; ai < 4; ai++)
        #pragma unroll
        for (int bj = 0; bj < 8; bj++)
            #pragma unroll
            for (int cq = 0; cq < 4; cq++) acc[ai][bj][cq] = 0.f;

    auto pf = [&](int s, int kt) {
        char* sA = smem + s * STG;
        char* sB = sA + ASTG;
        const float4* ag = Abase + (size_t)kt * 1024;
        const float4* bg = Bbase + (size_t)kt * 2048;
        #pragma unroll
        for (int i = 0; i < 4; i++)
            cp16(sA + (tid + i * 256) * 16, ag + tid + i * 256);
        #pragma unroll
        for (int i = 0; i < 8; i++)
            cp16(sB + (tid + i * 256) * 16, bg + tid + i * 256);
    };

    pf(0, 0); CP_COMMIT();
    pf(1, 1); CP_COMMIT();

    int s = 0;
    for (int kt = 0; kt < nkt; kt++) {
        CP_WAIT1();
        __syncthreads();

        const uint4* sA = (const uint4*)(smem + s * STG);
        const uint4* sB = (const uint4*)(smem + s * STG + ASTG);
        #pragma unroll
        for (int kkk = 0; kkk < 4; kkk++) {
            const int ao = (kkk >> 1) * 512  + ((kkk & 1) * 8  + wm * 4) * 32 + lane;
            const int bo = (kkk >> 1) * 1024 + ((kkk & 1) * 16 + wn * 4) * 32 + lane;
            uint4 af[4], bf[4];
            #pragma unroll
            for (int mi = 0; mi < 4; mi++) af[mi] = sA[ao + mi * 32];
            #pragma unroll
            for (int jp = 0; jp < 4; jp++) bf[jp] = sB[bo + jp * 32];
            #pragma unroll
            for (int mi = 0; mi < 4; mi++)
                #pragma unroll
                for (int jp = 0; jp < 4; jp++) {
                    MMA(acc[mi][jp * 2],     af[mi], bf[jp].x, bf[jp].y);
                    MMA(acc[mi][jp * 2 + 1], af[mi], bf[jp].z, bf[jp].w);
                }
        }

        // prefetch into the stage consumed at iteration kt-1 (safe: all threads
        // passed the barrier at the top of this iteration)
        if (kt + 2 < nkt) pf((kt + 2) % NSTG, kt + 2);
        CP_COMMIT();
        if (++s == NSTG) s = 0;
    }
    __syncthreads();

    // ---------------- epilogue (staged per 64-row half) ----------------
    const int lq = lane >> 2, lr = lane & 3;
    float* sC = (float*)smem;                 // [64][260]

    for (int h = 0; h < 2; h++) {
        if (wm == h) {
            #pragma unroll
            for (int mi = 0; mi < 4; mi++)
                #pragma unroll
                for (int j = 0; j < 8; j++) {
                    const int r0 = mi * 16 + lq;
                    const int c0 = wn * 64 + j * 8 + lr * 2;
                    sC[r0 * 260 + c0]           = acc[mi][j][0];
                    sC[r0 * 260 + c0 + 1]       = acc[mi][j][1];
                    sC[(r0 + 8) * 260 + c0]     = acc[mi][j][2];
                    sC[(r0 + 8) * 260 + c0 + 1] = acc[mi][j][3];
                }
        }
        __syncthreads();

        if constexpr (MODE == 0) {
            // emit packed-A float4s for the gates GEMM
            #pragma unroll 4
            for (int it = 0; it < 16; it++) {
                const int idx = it * 256 + tid;        // 0..4095
                const int cp  = idx & 127;             // col-pair id
                const int rp  = idx >> 7;              // 0..31 row-pair id
                const int g8  = cp >> 2, lr2 = cp & 3;
                const int lc0 = g8 * 8 + lr2;
                const int g16l = rp >> 3, lq2 = rp & 7;
                const int rl0 = g16l * 16 + lq2;       // local row in half
                const float v00 = rna(sC[rl0 * 260 + lc0]);
                const float v10 = rna(sC[(rl0 + 8) * 260 + lc0]);
                const float v01 = rna(sC[rl0 * 260 + lc0 + 4]);
                const float v11 = rna(sC[(rl0 + 8) * 260 + lc0 + 4]);
                const int gc   = bn0 + lc0;
                const int bi   = gc / PC;
                const int p    = gc - bi * PC;
                const int kidx = z * PC + p;
                const int g16  = (h * 64 + rl0) >> 4;  // global 16-row group
                const int mt   = bi * (Nn / 128) + (bm0 >> 7);
                const int kt2  = kidx >> 4;
                const int kk2  = (kidx >> 3) & 1;
                const int lane2 = lq2 * 4 + lr2;
                const size_t f4i =
                    (((size_t)mt * nktOut + kt2) * 16 + (kk2 * 8 + g16)) * 32 + lane2;
                outP[f4i] = make_float4(v00, v10, v01, v11);
            }
        } else {
            // fused bias + LSTM; cols 0..63=i, 64..127=f, 128..191=o, 192..255=g
            #pragma unroll 4
            for (int it = 0; it < 16; it++) {
                const int idx  = it * 256 + tid;       // 0..4095
                const int row  = idx >> 6;             // 0..63
                const int hc   = idx & 63;
                const float gi = sC[row * 260 + hc]        + __ldg(bias + hc);
                const float gf = sC[row * 260 + 64 + hc]   + __ldg(bias + 64 + hc);
                const float go = sC[row * 260 + 128 + hc]  + __ldg(bias + 128 + hc);
                const float gg = sC[row * 260 + 192 + hc]  + __ldg(bias + 192 + hc);
                const size_t m  = (size_t)bm0 + h * 64 + row;
                const size_t ix = m * Hh + hc;
                const float ct = sigm(gf) * cpre[ix] + sigm(gi) * tanhf(gg);
                const float ht = sigm(go) * tanhf(ct);
                ho1[ix] = ht;
                if (ho2)  ho2[ix]  = ht;
                co[ix] = ct;
                if (hscr) hscr[ix] = ht;
            }
        }
        __syncthreads();
    }
}

// ---------------------------------------------------------------------------
// prep/pack kernels (all write tf32-rounded values)
// ---------------------------------------------------------------------------
// G -> packed A: idx = [z][mt(5b)][kt16(8b)][blk(4b)][lane(5b)]
__global__ void packG_k(const float* __restrict__ G)
{
    const int idx = blockIdx.x * blockDim.x + threadIdx.x;
    if (idx >= Kc * 32 * 256 * 16 * 32) return;
    const int lane = idx & 31;
    const int blk  = (idx >> 5) & 15;
    const int kt   = (idx >> 9) & 255;
    const int mt   = (idx >> 17) & 31;
    const int z    = idx >> 22;
    const int kk = blk >> 3, g16 = blk & 7;
    const int lq = lane >> 2, lr = lane & 3;
    const int r = mt * 128 + g16 * 16 + lq;
    const int c = kt * 16 + kk * 8 + lr;
    const float* Gz = G + (size_t)z * Nn * Nn;
    g_GP[idx] = make_float4(
        rna(Gz[(size_t)r * Nn + c]),       rna(Gz[(size_t)(r + 8) * Nn + c]),
        rna(Gz[(size_t)r * Nn + c + 4]),   rna(Gz[(size_t)(r + 8) * Nn + c + 4]));
}

// comb value fetchers
__device__ __forceinline__ float comb0_val(const float* x, const float* h0, int m, int col) {
    const int b = col / P0, p = col - b * P0;
    return (p < Cc) ? x[((size_t)b * Nn + m) * Cc + p]
                    : h0[((size_t)b * Nn + m) * Hh + (p - Cc)];
}
__device__ __forceinline__ float comb1_val(const float* h1, int m, int col) {
    const int b = col >> 7, p = col & 127;
    return (p < Hh) ? g_ht0[((size_t)b * Nn + m) * Hh + p]
                    : h1[((size_t)b * Nn + m) * Hh + (p - Hh)];
}

// comb -> packed B: idx = [nt][kt16(8b)][blk(5b)][lane(5b)]
__global__ void packC0_k(const float* __restrict__ x, const float* __restrict__ h0, int total)
{
    const int idx = blockIdx.x * blockDim.x + threadIdx.x;
    if (idx >= total) return;
    const int lane = idx & 31;
    const int blk  = (idx >> 5) & 31;
    const int kt   = (idx >> 10) & 255;
    const int nt   = idx >> 18;
    const int kk = blk >> 4, jp = blk & 15;
    const int lq = lane >> 2, lr = lane & 3;
    const int m0 = kt * 16 + kk * 8 + lr;
    const int c0 = nt * 256 + jp * 16 + lq;
    g_combP[idx] = make_float4(
        rna(comb0_val(x, h0, m0, c0)),     rna(comb0_val(x, h0, m0 + 4, c0)),
        rna(comb0_val(x, h0, m0, c0 + 8)), rna(comb0_val(x, h0, m0 + 4, c0 + 8)));
}
__global__ void packC1_k(const float* __restrict__ h1, int total)
{
    const int idx = blockIdx.x * blockDim.x + threadIdx.x;
    if (idx >= total) return;
    const int lane = idx & 31;
    const int blk  = (idx >> 5) & 31;
    const int kt   = (idx >> 10) & 255;
    const int nt   = idx >> 18;
    const int kk = blk >> 4, jp = blk & 15;
    const int lq = lane >> 2, lr = lane & 3;
    const int m0 = kt * 16 + kk * 8 + lr;
    const int c0 = nt * 256 + jp * 16 + lq;
    g_combP[idx] = make_float4(
        rna(comb1_val(h1, m0, c0)),     rna(comb1_val(h1, m0 + 4, c0)),
        rna(comb1_val(h1, m0, c0 + 8)), rna(comb1_val(h1, m0 + 4, c0 + 8)));
}

// W -> packed B: idx = [kt16][blk(5b)][lane(5b)]; W is [KP][256] row-major.
// Rows k >= KP are zero-filled (layer-0 K padded 240 -> 256).
__global__ void packW_k(const float* __restrict__ W, int KP, int total)
{
    const int idx = blockIdx.x * blockDim.x + threadIdx.x;
    if (idx >= total) return;
    const int lane = idx & 31;
    const int blk  = (idx >> 5) & 31;
    const int kt   = idx >> 10;
    const int kk = blk >> 4, jp = blk & 15;
    const int lq = lane >> 2, lr = lane & 3;
    const int k0 = kt * 16 + kk * 8 + lr;
    const int g0 = jp * 16 + lq;
    const float w0 = (k0     < KP) ? rna(W[(size_t)k0       * GH + g0])     : 0.f;
    const float w1 = (k0 + 4 < KP) ? rna(W[(size_t)(k0 + 4) * GH + g0])     : 0.f;
    const float w2 = (k0     < KP) ? rna(W[(size_t)k0       * GH + g0 + 8]) : 0.f;
    const float w3 = (k0 + 4 < KP) ? rna(W[(size_t)(k0 + 4) * GH + g0 + 8]) : 0.f;
    g_WtP[idx] = make_float4(w0, w1, w2, w3);
}

// ---------------------------------------------------------------------------
extern "C" void kernel_launch(void* const* d_in, const int* in_sizes, int n_in,
                              void* d_out, int out_size)
{
    (void)in_sizes; (void)n_in; (void)out_size;
    const float* G  = (const float*)d_in[0];
    const float* xt = (const float*)d_in[1];
    const float* h0 = (const float*)d_in[2];
    const float* h1 = (const float*)d_in[3];
    const float* c0 = (const float*)d_in[4];
    const float* c1 = (const float*)d_in[5];
    const float* W0 = (const float*)d_in[6];
    const float* b0 = (const float*)d_in[7];
    const float* W1 = (const float*)d_in[8];
    const float* b1 = (const float*)d_in[9];
    float* out = (float*)d_out;

    float4 *GP, *combP, *suppP, *WtP;
    float  *ht0;
    cudaGetSymbolAddress((void**)&GP,    g_GP);
    cudaGetSymbolAddress((void**)&combP, g_combP);
    cudaGetSymbolAddress((void**)&suppP, g_suppP);
    cudaGetSymbolAddress((void**)&WtP,   g_WtP);
    cudaGetSymbolAddress((void**)&ht0,   g_ht0);

    cudaFuncSetAttribute(gemm_pk<0, P0>, cudaFuncAttributeMaxDynamicSharedMemorySize, SMEM_MAIN);
    cudaFuncSetAttribute(gemm_pk<0, P1>, cudaFuncAttributeMaxDynamicSharedMemorySize, SMEM_MAIN);
    cudaFuncSetAttribute(gemm_pk<1, P0>, cudaFuncAttributeMaxDynamicSharedMemorySize, SMEM_MAIN);

    const size_t S = (size_t)ROWS * Hh;   // 8388608 per output slot
    const int nktG    = Nn / 32;          // 128 (32-K tiles)
    const int nkt0_32 = 8;                // layer-0 gates K padded to 256
    const int nkt1_32 = 12;               // layer-1 gates K = 384
    const int nktOut0 = 16;               // 16-K blocks (padded)
    const int nktOut1 = 24;

    // pack G (both layers use it)
    packG_k<<<(Kc * 32 * 256 * 16 * 32) / 256, 256>>>(G);

    // ---- layer 0 ----
    {
        const int tot = (NC0 / 256) * 256 * 32 * 32;   // nt=10, kt=256, 1024 f4/blk
        packC0_k<<<(tot + 255) / 256, 256>>>(xt, h0, tot);
    }
    gemm_pk<0, P0><<<dim3(NC0 / BN, Nn / BM, Kc), 256, SMEM_MAIN>>>(
        GP, combP, nktG, suppP, nktOut0,
        nullptr, nullptr, nullptr, nullptr, nullptr, nullptr);
    {
        const int tot = nktOut0 * 1024;
        packW_k<<<(tot + 255) / 256, 256>>>(W0, KP0, tot);
    }
    gemm_pk<1, P0><<<dim3(1, ROWS / BM, 1), 256, SMEM_MAIN>>>(
        suppP, WtP, nkt0_32, nullptr, 0,
        b0, c0, out + S, nullptr, out + 3 * S, ht0);

    // ---- layer 1 ----
    {
        const int tot = (NC1 / 256) * 256 * 32 * 32;   // nt=16
        packC1_k<<<(tot + 255) / 256, 256>>>(h1, tot);
    }
    gemm_pk<0, P1><<<dim3(NC1 / BN, Nn / BM, Kc), 256, SMEM_MAIN>>>(
        GP, combP, nktG, suppP, nktOut1,
        nullptr, nullptr, nullptr, nullptr, nullptr, nullptr);
    {
        const int tot = nktOut1 * 1024;
        packW_k<<<(tot + 255) / 256, 256>>>(W1, KP1, tot);
    }
    gemm_pk<1, P0><<<dim3(1, ROWS / BM, 1), 256, SMEM_MAIN>>>(
        suppP, WtP, nkt1_32, nullptr, 0,
        b1, c1, out, out + 2 * S, out + 4 * S, nullptr);
}

// round 11
// speedup vs baseline: 2.2880x; 1.6785x over previous
#include <cuda_runtime.h>
#include <cuda_fp16.h>
#include <math.h>
#include <stdint.h>

// ---------------- problem constants ----------------
#define Nn    4096
#define Bb    32
#define Cc    16
#define Hh    64
#define Kc    3
#define P0    80
#define P1    128
#define NC0   (Bb*P0)     // 2560
#define NC1   (Bb*P1)     // 4096
#define KP0   (Kc*P0)     // 240
#define KP1   (Kc*P1)     // 384
#define GH    256
#define ROWS  (Bb*Nn)     // 131072

// ---------------- GEMM tiling (fp16 operands, fp32 accum) ----------------
#define BM   128
#define BN   256
#define NSTG 4
#define ASTG 8192                  // 128x32 fp16 packed A
#define BSTG 16384                 // 32x256 fp16 packed B
#define STG  (ASTG + BSTG)         // 24576
#define SMEM_MAIN (NSTG * STG)     // 98304 (epilogue reuses 66.6KB of it)

// ---------------- scratch (__device__ globals, fragment-packed fp16) -------
// A for supp GEMM: [z(3)][mt(32)][kb16(256)][g16(8)][lane(32)] uint4
__device__ uint4 g_GPh   [(size_t)Kc * 32 * 256 * 8 * 32];     // 100.7 MB
// B (comb): [nt(<=16)][kb16(256)][jq(16)][lane(32)] uint4
__device__ uint4 g_combPh[(size_t)16 * 256 * 16 * 32];         // 33.5 MB
// A for gates GEMM: [mt(1024)][kb16(<=24)][g16(8)][lane(32)] uint4
__device__ uint4 g_suppPh[(size_t)1024 * 24 * 8 * 32];         // 100.7 MB
// B (W): [kb16(<=24)][jq(16)][lane(32)] uint4
__device__ uint4 g_WtPh  [(size_t)24 * 16 * 32];
__device__ float g_ht0   [(size_t)ROWS * Hh];                  // 33.5 MB

// ---------------- helpers ----------------
__device__ __forceinline__ float sigm(float x) { return 1.f / (1.f + expf(-x)); }

__device__ __forceinline__ uint32_t h2pack(float a, float b) {
    __half2 h = __halves2half2(__float2half_rn(a), __float2half_rn(b));
    return *reinterpret_cast<uint32_t*>(&h);
}

__device__ __forceinline__ void cp16(void* s, const void* g) {
    uint32_t a;
    asm("{ .reg .u64 t; cvta.to.shared.u64 t, %1; cvt.u32.u64 %0, t; }" : "=r"(a) : "l"(s));
    asm volatile("cp.async.cg.shared.global [%0], [%1], 16;" :: "r"(a), "l"(g));
}
#define CP_COMMIT() asm volatile("cp.async.commit_group;")
#define CP_WAIT2()  asm volatile("cp.async.wait_group 2;")

// fp16 MMA: D(f32) += A(f16) * B(f16); m16n8k16
#define MMAH(accq, af, b0, b1) \
    asm volatile("mma.sync.aligned.m16n8k16.row.col.f32.f16.f16.f32 " \
        "{%0,%1,%2,%3}, {%4,%5,%6,%7}, {%8,%9}, {%0,%1,%2,%3};" \
        : "+f"((accq)[0]), "+f"((accq)[1]), "+f"((accq)[2]), "+f"((accq)[3]) \
        : "r"((af).x), "r"((af).y), "r"((af).z), "r"((af).w), "r"(b0), "r"(b1))

// ---------------------------------------------------------------------------
// Packed-fragment fp16 GEMM. C[128x256] per CTA; K consumed in 32-wide tiles
// (two 16-K fragment blocks). 8 warps (2x4), warp tile 64x64.
// Per k16 step per warp: 4 LDS.128 (A) + 4 LDS.128 (B) + 32 MMA.
// A block (per mtile,kb16): [g16(8)][lane(32)] uint4 =
//   {h2(r,c / r,c+1), h2(r+8,c..), h2(r,c+8..), h2(r+8,c+8..)}, c=t*2, r=g16*16+g
// B block (per ntile,kb16): [jq(16)][lane(32)] uint4 =
//   {b0,b1 of n8-tile 2jq ; b0,b1 of n8-tile 2jq+1}
// MODE 0: emit supp as packed fp16 A-fragments for the gates GEMM.
// MODE 1: fused bias + LSTM.
// nkt in 32-K tiles; nktOut (MODE 0 / gates layout) in 16-K blocks.
// ---------------------------------------------------------------------------
template<int MODE, int PC>
__global__ void __launch_bounds__(256, 1)
gemm_fp16(const uint4* __restrict__ Ap, const uint4* __restrict__ Bp,
          int nkt, uint4* __restrict__ outP, int nktOut,
          const float* __restrict__ bias, const float* __restrict__ cpre,
          float* __restrict__ ho1, float* __restrict__ ho2,
          float* __restrict__ co,  float* __restrict__ hscr)
{
    extern __shared__ char smem[];
    const int tid  = threadIdx.x;
    const int wid  = tid >> 5, lane = tid & 31;
    const int wm   = wid >> 2, wn = wid & 3;
    const int bm0  = blockIdx.y * BM;
    const int bn0  = blockIdx.x * BN;
    const int zz   = blockIdx.z;

    // uint4 units: A kb16 block = 256, B kb16 block = 512
    const uint4* Abase = Ap + ((size_t)zz * gridDim.y + blockIdx.y) * (size_t)(2 * nkt) * 256;
    const uint4* Bbase = Bp + (size_t)blockIdx.x * (size_t)(2 * nkt) * 512;

    float acc[4][8][4];
    #pragma unroll
    for (int ai = 0; ai < 4; ai++)
        #pragma unroll
        for (int bj = 0; bj < 8; bj++)
            #pragma unroll
            for (int cq = 0; cq < 4; cq++) acc[ai][bj][cq] = 0.f;

    auto pf = [&](int sg, int kt) {
        char* sA = smem + sg * STG;
        char* sB = sA + ASTG;
        const uint4* ag = Abase + (size_t)kt * 512;
        const uint4* bg = Bbase + (size_t)kt * 1024;
        cp16(sA + tid * 16,         ag + tid);
        cp16(sA + (tid + 256) * 16, ag + tid + 256);
        #pragma unroll
        for (int i = 0; i < 4; i++)
            cp16(sB + (tid + i * 256) * 16, bg + tid + i * 256);
    };

    pf(0, 0); CP_COMMIT();
    pf(1, 1); CP_COMMIT();
    pf(2, 2); CP_COMMIT();

    int sg = 0;
    for (int kt = 0; kt < nkt; kt++) {
        CP_WAIT2();
        __syncthreads();

        const uint4* sA = (const uint4*)(smem + sg * STG);
        const uint4* sB = (const uint4*)(smem + sg * STG + ASTG);
        #pragma unroll
        for (int k2 = 0; k2 < 2; k2++) {
            uint4 af[4], bf[4];
            #pragma unroll
            for (int mi = 0; mi < 4; mi++)
                af[mi] = sA[k2 * 256 + (wm * 4 + mi) * 32 + lane];
            #pragma unroll
            for (int jq = 0; jq < 4; jq++)
                bf[jq] = sB[k2 * 512 + (wn * 4 + jq) * 32 + lane];
            #pragma unroll
            for (int mi = 0; mi < 4; mi++)
                #pragma unroll
                for (int jq = 0; jq < 4; jq++) {
                    MMAH(acc[mi][jq * 2],     af[mi], bf[jq].x, bf[jq].y);
                    MMAH(acc[mi][jq * 2 + 1], af[mi], bf[jq].z, bf[jq].w);
                }
        }

        // prefetch into the stage consumed at iteration kt-1 (safe after the
        // barrier at the top of this iteration)
        if (kt + 3 < nkt) pf((kt + 3) & 3, kt + 3);
        CP_COMMIT();
        sg = (sg + 1) & 3;
    }
    __syncthreads();

    // ---------------- epilogue (staged per 64-row half) ----------------
    const int lq = lane >> 2, lr = lane & 3;
    float* sC = (float*)smem;                 // [64][260]

    for (int h = 0; h < 2; h++) {
        if (wm == h) {
            #pragma unroll
            for (int mi = 0; mi < 4; mi++)
                #pragma unroll
                for (int j = 0; j < 8; j++) {
                    const int r0 = mi * 16 + lq;
                    const int c0 = wn * 64 + j * 8 + lr * 2;
                    sC[r0 * 260 + c0]           = acc[mi][j][0];
                    sC[r0 * 260 + c0 + 1]       = acc[mi][j][1];
                    sC[(r0 + 8) * 260 + c0]     = acc[mi][j][2];
                    sC[(r0 + 8) * 260 + c0 + 1] = acc[mi][j][3];
                }
        }
        __syncthreads();

        if constexpr (MODE == 0) {
            // emit packed fp16 A-fragments for the gates GEMM
            // 2048 uint4 per half: [lkb(16)][g16h(4)][lane(32)]
            #pragma unroll 4
            for (int it = 0; it < 8; it++) {
                const int idx  = it * 256 + tid;       // 0..2047
                const int ln2  = idx & 31;
                const int g16h = (idx >> 5) & 3;
                const int lkb  = idx >> 7;             // 0..15
                const int gg = ln2 >> 2, tt = ln2 & 3;
                const int rl0 = g16h * 16 + gg;        // local row in half
                const int c0  = lkb * 16 + tt * 2;
                uint4 ha;
                ha.x = h2pack(sC[rl0 * 260 + c0],           sC[rl0 * 260 + c0 + 1]);
                ha.y = h2pack(sC[(rl0 + 8) * 260 + c0],     sC[(rl0 + 8) * 260 + c0 + 1]);
                ha.z = h2pack(sC[rl0 * 260 + c0 + 8],       sC[rl0 * 260 + c0 + 9]);
                ha.w = h2pack(sC[(rl0 + 8) * 260 + c0 + 8], sC[(rl0 + 8) * 260 + c0 + 9]);
                const int gcb  = bn0 + lkb * 16;       // 16-aligned col block
                const int bi   = gcb / PC;
                const int kidx = zz * PC + (gcb - bi * PC);
                const int kt2  = kidx >> 4;
                const int mtg  = bi * (Nn / 128) + (bm0 >> 7);
                const int g16g = h * 4 + g16h;
                const size_t f4i =
                    (((size_t)mtg * nktOut + kt2) * 8 + g16g) * 32 + ln2;
                outP[f4i] = ha;
            }
        } else {
            // fused bias + LSTM; cols 0..63=i, 64..127=f, 128..191=o, 192..255=g
            #pragma unroll 4
            for (int it = 0; it < 16; it++) {
                const int idx  = it * 256 + tid;       // 0..4095
                const int row  = idx >> 6;             // 0..63
                const int hc   = idx & 63;
                const float gi = sC[row * 260 + hc]        + __ldg(bias + hc);
                const float gf = sC[row * 260 + 64 + hc]   + __ldg(bias + 64 + hc);
                const float go = sC[row * 260 + 128 + hc]  + __ldg(bias + 128 + hc);
                const float gg = sC[row * 260 + 192 + hc]  + __ldg(bias + 192 + hc);
                const size_t m  = (size_t)bm0 + h * 64 + row;
                const size_t ix = m * Hh + hc;
                const float ct = sigm(gf) * cpre[ix] + sigm(gi) * tanhf(gg);
                const float ht = sigm(go) * tanhf(ct);
                ho1[ix] = ht;
                if (ho2)  ho2[ix]  = ht;
                co[ix] = ct;
                if (hscr) hscr[ix] = ht;
            }
        }
        __syncthreads();
    }
}

// ---------------------------------------------------------------------------
// pack kernels (fp16 fragments, round-to-nearest)
// ---------------------------------------------------------------------------
// G -> A-fragments: idx = [z(2b)][mt(5b)][kb(8b)][g16(3b)][lane(5b)]
__global__ void packG_k(const float* __restrict__ G)
{
    const int idx = blockIdx.x * blockDim.x + threadIdx.x;
    if (idx >= Kc * 32 * 256 * 8 * 32) return;
    const int lane = idx & 31;
    const int g16  = (idx >> 5) & 7;
    const int kb   = (idx >> 8) & 255;
    const int mt   = (idx >> 16) & 31;
    const int zi   = idx >> 21;
    const int gg = lane >> 2, tt = lane & 3;
    const int r = mt * 128 + g16 * 16 + gg;
    const int c = kb * 16 + tt * 2;
    const float* Gz = G + (size_t)zi * Nn * Nn;
    uint4 v;
    v.x = h2pack(Gz[(size_t)r * Nn + c],           Gz[(size_t)r * Nn + c + 1]);
    v.y = h2pack(Gz[(size_t)(r + 8) * Nn + c],     Gz[(size_t)(r + 8) * Nn + c + 1]);
    v.z = h2pack(Gz[(size_t)r * Nn + c + 8],       Gz[(size_t)r * Nn + c + 9]);
    v.w = h2pack(Gz[(size_t)(r + 8) * Nn + c + 8], Gz[(size_t)(r + 8) * Nn + c + 9]);
    g_GPh[idx] = v;
}

// comb value fetchers
__device__ __forceinline__ float comb0_val(const float* x, const float* h0, int m, int col) {
    const int b = col / P0, p = col - b * P0;
    return (p < Cc) ? x[((size_t)b * Nn + m) * Cc + p]
                    : h0[((size_t)b * Nn + m) * Hh + (p - Cc)];
}
__device__ __forceinline__ float comb1_val(const float* h1, int m, int col) {
    const int b = col >> 7, p = col & 127;
    return (p < Hh) ? g_ht0[((size_t)b * Nn + m) * Hh + p]
                    : h1[((size_t)b * Nn + m) * Hh + (p - Hh)];
}

// comb -> B-fragments: idx = [nt][kb(8b)][jq(4b)][lane(5b)]
__global__ void packC0_k(const float* __restrict__ x, const float* __restrict__ h0, int total)
{
    const int idx = blockIdx.x * blockDim.x + threadIdx.x;
    if (idx >= total) return;
    const int lane = idx & 31;
    const int jq   = (idx >> 5) & 15;
    const int kb   = (idx >> 9) & 255;
    const int nt   = idx >> 17;
    const int gg = lane >> 2, tt = lane & 3;
    const int na = nt * 256 + jq * 16 + gg;
    const int nb = na + 8;
    const int k0 = kb * 16 + tt * 2;
    uint4 v;
    v.x = h2pack(comb0_val(x, h0, k0,     na), comb0_val(x, h0, k0 + 1, na));
    v.y = h2pack(comb0_val(x, h0, k0 + 8, na), comb0_val(x, h0, k0 + 9, na));
    v.z = h2pack(comb0_val(x, h0, k0,     nb), comb0_val(x, h0, k0 + 1, nb));
    v.w = h2pack(comb0_val(x, h0, k0 + 8, nb), comb0_val(x, h0, k0 + 9, nb));
    g_combPh[idx] = v;
}
__global__ void packC1_k(const float* __restrict__ h1, int total)
{
    const int idx = blockIdx.x * blockDim.x + threadIdx.x;
    if (idx >= total) return;
    const int lane = idx & 31;
    const int jq   = (idx >> 5) & 15;
    const int kb   = (idx >> 9) & 255;
    const int nt   = idx >> 17;
    const int gg = lane >> 2, tt = lane & 3;
    const int na = nt * 256 + jq * 16 + gg;
    const int nb = na + 8;
    const int k0 = kb * 16 + tt * 2;
    uint4 v;
    v.x = h2pack(comb1_val(h1, k0,     na), comb1_val(h1, k0 + 1, na));
    v.y = h2pack(comb1_val(h1, k0 + 8, na), comb1_val(h1, k0 + 9, na));
    v.z = h2pack(comb1_val(h1, k0,     nb), comb1_val(h1, k0 + 1, nb));
    v.w = h2pack(comb1_val(h1, k0 + 8, nb), comb1_val(h1, k0 + 9, nb));
    g_combPh[idx] = v;
}

// W -> B-fragments: idx = [kb][jq(4b)][lane(5b)]; W is [KP][256] row-major,
// rows k >= KP zero-filled (layer-0 K padded 240 -> 256).
__global__ void packW_k(const float* __restrict__ W, int KPv, int total)
{
    const int idx = blockIdx.x * blockDim.x + threadIdx.x;
    if (idx >= total) return;
    const int lane = idx & 31;
    const int jq   = (idx >> 5) & 15;
    const int kb   = idx >> 9;
    const int gg = lane >> 2, tt = lane & 3;
    const int na = jq * 16 + gg;
    const int nb = na + 8;
    const int k0 = kb * 16 + tt * 2;
    auto wv = [&](int k, int n) -> float {
        return (k < KPv) ? W[(size_t)k * GH + n] : 0.f;
    };
    uint4 v;
    v.x = h2pack(wv(k0, na),     wv(k0 + 1, na));
    v.y = h2pack(wv(k0 + 8, na), wv(k0 + 9, na));
    v.z = h2pack(wv(k0, nb),     wv(k0 + 1, nb));
    v.w = h2pack(wv(k0 + 8, nb), wv(k0 + 9, nb));
    g_WtPh[idx] = v;
}

// ---------------------------------------------------------------------------
extern "C" void kernel_launch(void* const* d_in, const int* in_sizes, int n_in,
                              void* d_out, int out_size)
{
    (void)in_sizes; (void)n_in; (void)out_size;
    const float* G  = (const float*)d_in[0];
    const float* xt = (const float*)d_in[1];
    const float* h0 = (const float*)d_in[2];
    const float* h1 = (const float*)d_in[3];
    const float* c0 = (const float*)d_in[4];
    const float* c1 = (const float*)d_in[5];
    const float* W0 = (const float*)d_in[6];
    const float* b0 = (const float*)d_in[7];
    const float* W1 = (const float*)d_in[8];
    const float* b1 = (const float*)d_in[9];
    float* out = (float*)d_out;

    uint4 *GP, *combP, *suppP, *WtP;
    float *ht0;
    cudaGetSymbolAddress((void**)&GP,    g_GPh);
    cudaGetSymbolAddress((void**)&combP, g_combPh);
    cudaGetSymbolAddress((void**)&suppP, g_suppPh);
    cudaGetSymbolAddress((void**)&WtP,   g_WtPh);
    cudaGetSymbolAddress((void**)&ht0,   g_ht0);

    cudaFuncSetAttribute(gemm_fp16<0, P0>, cudaFuncAttributeMaxDynamicSharedMemorySize, SMEM_MAIN);
    cudaFuncSetAttribute(gemm_fp16<0, P1>, cudaFuncAttributeMaxDynamicSharedMemorySize, SMEM_MAIN);
    cudaFuncSetAttribute(gemm_fp16<1, P0>, cudaFuncAttributeMaxDynamicSharedMemorySize, SMEM_MAIN);

    const size_t S = (size_t)ROWS * Hh;   // 8388608 per output slot
    const int nktG32  = Nn / 32;          // 128 (32-K tiles, supp GEMM)
    const int nkt0_32 = 8;                // gates layer0, K padded 240 -> 256
    const int nkt1_32 = 12;               // gates layer1, K = 384
    const int nktOut0 = 16;               // 16-K blocks in suppP (layer0)
    const int nktOut1 = 24;

    // pack G (both layers)
    packG_k<<<(Kc * 32 * 256 * 8 * 32) / 256, 256>>>(G);

    // ---- layer 0 ----
    {
        const int tot = (NC0 / 256) * 256 * 16 * 32;   // nt=10
        packC0_k<<<(tot + 255) / 256, 256>>>(xt, h0, tot);
    }
    gemm_fp16<0, P0><<<dim3(NC0 / BN, Nn / BM, Kc), 256, SMEM_MAIN>>>(
        GP, combP, nktG32, suppP, nktOut0,
        nullptr, nullptr, nullptr, nullptr, nullptr, nullptr);
    {
        const int tot = nktOut0 * 16 * 32;
        packW_k<<<(tot + 255) / 256, 256>>>(W0, KP0, tot);
    }
    gemm_fp16<1, P0><<<dim3(1, ROWS / BM, 1), 256, SMEM_MAIN>>>(
        suppP, WtP, nkt0_32, nullptr, 0,
        b0, c0, out + S, nullptr, out + 3 * S, ht0);

    // ---- layer 1 ----
    {
        const int tot = (NC1 / 256) * 256 * 16 * 32;   // nt=16
        packC1_k<<<(tot + 255) / 256, 256>>>(h1, tot);
    }
    gemm_fp16<0, P1><<<dim3(NC1 / BN, Nn / BM, Kc), 256, SMEM_MAIN>>>(
        GP, combP, nktG32, suppP, nktOut1,
        nullptr, nullptr, nullptr, nullptr, nullptr, nullptr);
    {
        const int tot = nktOut1 * 16 * 32;
        packW_k<<<(tot + 255) / 256, 256>>>(W1, KP1, tot);
    }
    gemm_fp16<1, P0><<<dim3(1, ROWS / BM, 1), 256, SMEM_MAIN>>>(
        suppP, WtP, nkt1_32, nullptr, 0,
        b1, c1, out, out + 2 * S, out + 4 * S, nullptr);
}

// round 13
// speedup vs baseline: 2.4630x; 1.0765x over previous
#include <cuda_runtime.h>
#include <cuda_fp16.h>
#include <math.h>
#include <stdint.h>

// ---------------- problem constants ----------------
#define Nn    4096
#define Bb    32
#define Cc    16
#define Hh    64
#define Kc    3
#define P0    80
#define P1    128
#define NC0   (Bb*P0)     // 2560
#define NC1   (Bb*P1)     // 4096
#define KP0   (Kc*P0)     // 240
#define KP1   (Kc*P1)     // 384
#define GH    256
#define ROWS  (Bb*Nn)     // 131072

// ---------------- scratch (__device__ globals, fragment-packed fp16) -------
// A for supp GEMM: [z(3)][mt(32)][kb16(256)][g16(8)][lane(32)] uint4
__device__ uint4 g_GPh   [(size_t)Kc * 32 * 256 * 8 * 32];     // 100.7 MB
// B (comb): [nt(<=16)][kb16(256)][jq(16)][lane(32)] uint4
__device__ uint4 g_combPh[(size_t)16 * 256 * 16 * 32];         // 33.5 MB
// A for gates GEMM: [mt(1024)][kb16(<=24)][g16(8)][lane(32)] uint4
__device__ uint4 g_suppPh[(size_t)1024 * 24 * 8 * 32];         // 100.7 MB
// B (W): [kb16(<=24)][jq(16)][lane(32)] uint4
__device__ uint4 g_WtPh  [(size_t)24 * 16 * 32];
__device__ float g_ht0   [(size_t)ROWS * Hh];                  // 33.5 MB

// ---------------- helpers ----------------
__device__ __forceinline__ float sigm(float x) { return 1.f / (1.f + expf(-x)); }

__device__ __forceinline__ uint32_t h2pack(float a, float b) {
    __half2 h = __halves2half2(__float2half_rn(a), __float2half_rn(b));
    return *reinterpret_cast<uint32_t*>(&h);
}

__device__ __forceinline__ void cp16(void* s, const void* g) {
    uint32_t a;
    asm("{ .reg .u64 t; cvta.to.shared.u64 t, %1; cvt.u32.u64 %0, t; }" : "=r"(a) : "l"(s));
    asm volatile("cp.async.cg.shared.global [%0], [%1], 16;" :: "r"(a), "l"(g));
}
#define CP_COMMIT() asm volatile("cp.async.commit_group;")
#define CP_WAIT2()  asm volatile("cp.async.wait_group 2;")

// fp16 MMA: D(f32) += A(f16) * B(f16); m16n8k16
#define MMAH(accq, af, b0, b1) \
    asm volatile("mma.sync.aligned.m16n8k16.row.col.f32.f16.f16.f32 " \
        "{%0,%1,%2,%3}, {%4,%5,%6,%7}, {%8,%9}, {%0,%1,%2,%3};" \
        : "+f"((accq)[0]), "+f"((accq)[1]), "+f"((accq)[2]), "+f"((accq)[3]) \
        : "r"((af).x), "r"((af).y), "r"((af).z), "r"((af).w), "r"(b0), "r"(b1))

// ===========================================================================
// supp GEMM: 128x128 tile, OCCUPANCY 2. 8 warps as 4(m) x 2(n), warp 32x64.
// 4-stage ring, 16KB/stage (A 8KB + B 8KB). acc = 64 regs/thread.
// Emits supp directly as packed fp16 A-fragments for the gates GEMM.
// nkt in 32-K tiles; nktOut in 16-K blocks (gates-layout K).
// ===========================================================================
#define S_ASTG 8192
#define S_STG  16384
#define S_SMEM 65536

template<int PC>
__global__ void __launch_bounds__(256, 2)
supp128(const uint4* __restrict__ Ap, const uint4* __restrict__ Bp,
        int nkt, uint4* __restrict__ outP, int nktOut)
{
    extern __shared__ char smem[];
    const int tid  = threadIdx.x;
    const int wid  = tid >> 5, lane = tid & 31;
    const int wm   = wid >> 1, wn = wid & 1;      // 4 x 2 warp grid
    const int bm0  = blockIdx.y * 128;
    const int bn0  = blockIdx.x * 128;
    const int zz   = blockIdx.z;

    // A: [z*32+mt] blocks of (2*nkt)*256 uint4; kb16 blocks contiguous
    const uint4* Abase = Ap + ((size_t)zz * 32 + (bm0 >> 7)) * (size_t)(2 * nkt) * 256;
    // B: [nt] blocks of (2*nkt)*512; take 8 contiguous jq-groups at jqoff
    const uint4* Bbase = Bp + (size_t)(bn0 >> 8) * (size_t)(2 * nkt) * 512
                            + (size_t)((bn0 >> 4) & 15) * 32;

    float acc[2][8][4];
    #pragma unroll
    for (int ai = 0; ai < 2; ai++)
        #pragma unroll
        for (int bj = 0; bj < 8; bj++)
            #pragma unroll
            for (int cq = 0; cq < 4; cq++) acc[ai][bj][cq] = 0.f;

    auto pf = [&](int sg, int kt) {
        char* sA = smem + sg * S_STG;
        char* sB = sA + S_ASTG;
        const uint4* ag = Abase + (size_t)(2 * kt) * 256;   // 512 contiguous
        const uint4* bg = Bbase + (size_t)(2 * kt) * 512;   // 2 x 256 strided
        cp16(sA + tid * 16,         ag + tid);
        cp16(sA + (tid + 256) * 16, ag + tid + 256);
        cp16(sB + tid * 16,         bg + tid);
        cp16(sB + (tid + 256) * 16, bg + 512 + tid);
    };

    pf(0, 0); CP_COMMIT();
    pf(1, 1); CP_COMMIT();
    pf(2, 2); CP_COMMIT();

    int sg = 0;
    for (int kt = 0; kt < nkt; kt++) {
        CP_WAIT2();
        __syncthreads();

        const uint4* sA = (const uint4*)(smem + sg * S_STG);
        const uint4* sB = (const uint4*)(smem + sg * S_STG + S_ASTG);
        #pragma unroll
        for (int k2 = 0; k2 < 2; k2++) {
            uint4 af[2], bf[4];
            #pragma unroll
            for (int mi = 0; mi < 2; mi++)
                af[mi] = sA[k2 * 256 + (wm * 2 + mi) * 32 + lane];
            #pragma unroll
            for (int jq = 0; jq < 4; jq++)
                bf[jq] = sB[k2 * 256 + (wn * 4 + jq) * 32 + lane];
            #pragma unroll
            for (int mi = 0; mi < 2; mi++)
                #pragma unroll
                for (int jq = 0; jq < 4; jq++) {
                    MMAH(acc[mi][jq * 2],     af[mi], bf[jq].x, bf[jq].y);
                    MMAH(acc[mi][jq * 2 + 1], af[mi], bf[jq].z, bf[jq].w);
                }
        }

        if (kt + 3 < nkt) pf((kt + 3) & 3, kt + 3);
        CP_COMMIT();
        sg = (sg + 1) & 3;
    }
    __syncthreads();

    // ---------------- epilogue: per 64-row half, via smem [64][132] --------
    const int lq = lane >> 2, lr = lane & 3;
    float* sC = (float*)smem;

    for (int h = 0; h < 2; h++) {
        if ((wm >> 1) == h) {
            #pragma unroll
            for (int mi = 0; mi < 2; mi++)
                #pragma unroll
                for (int j = 0; j < 8; j++) {
                    const int r0 = (wm & 1) * 32 + mi * 16 + lq;
                    const int c0 = wn * 64 + j * 8 + lr * 2;
                    sC[r0 * 132 + c0]           = acc[mi][j][0];
                    sC[r0 * 132 + c0 + 1]       = acc[mi][j][1];
                    sC[(r0 + 8) * 132 + c0]     = acc[mi][j][2];
                    sC[(r0 + 8) * 132 + c0 + 1] = acc[mi][j][3];
                }
        }
        __syncthreads();

        // 1024 uint4 per half: [lkb(8)][g16h(4)][lane(32)]
        #pragma unroll
        for (int it = 0; it < 4; it++) {
            const int idx  = it * 256 + tid;       // 0..1023
            const int ln2  = idx & 31;
            const int g16h = (idx >> 5) & 3;
            const int lkb  = idx >> 7;             // 0..7
            const int gg = ln2 >> 2, tt = ln2 & 3;
            const int rl0 = g16h * 16 + gg;
            const int c0  = lkb * 16 + tt * 2;
            uint4 ha;
            ha.x = h2pack(sC[rl0 * 132 + c0],           sC[rl0 * 132 + c0 + 1]);
            ha.y = h2pack(sC[(rl0 + 8) * 132 + c0],     sC[(rl0 + 8) * 132 + c0 + 1]);
            ha.z = h2pack(sC[rl0 * 132 + c0 + 8],       sC[rl0 * 132 + c0 + 9]);
            ha.w = h2pack(sC[(rl0 + 8) * 132 + c0 + 8], sC[(rl0 + 8) * 132 + c0 + 9]);
            const int gcb  = bn0 + lkb * 16;       // 16-aligned col block
            const int bi   = gcb / PC;
            const int kidx = zz * PC + (gcb - bi * PC);
            const int kt2  = kidx >> 4;
            const int mtg  = bi * (Nn / 128) + (bm0 >> 7);
            const int g16g = h * 4 + g16h;
            const size_t f4i =
                (((size_t)mtg * nktOut + kt2) * 8 + g16g) * 32 + ln2;
            outP[f4i] = ha;
        }
        __syncthreads();
    }
}

// ===========================================================================
// gates GEMM: 128x256 tile, occ 1 (needs all 4 gates in one CTA).
// 8 warps (2x4), warp tile 64x64. Fused bias + LSTM epilogue.
// ===========================================================================
#define G_ASTG 8192
#define G_BSTG 16384
#define G_STG  (G_ASTG + G_BSTG)
#define G_SMEM (4 * G_STG)         // 98304

__global__ void __launch_bounds__(256, 1)
gemm_gates(const uint4* __restrict__ Ap, const uint4* __restrict__ Bp,
           int nkt,
           const float* __restrict__ bias, const float* __restrict__ cpre,
           float* __restrict__ ho1, float* __restrict__ ho2,
           float* __restrict__ co,  float* __restrict__ hscr)
{
    extern __shared__ char smem[];
    const int tid  = threadIdx.x;
    const int wid  = tid >> 5, lane = tid & 31;
    const int wm   = wid >> 2, wn = wid & 3;
    const int bm0  = blockIdx.y * 128;

    const uint4* Abase = Ap + (size_t)blockIdx.y * (size_t)(2 * nkt) * 256;
    const uint4* Bbase = Bp;

    float acc[4][8][4];
    #pragma unroll
    for (int ai = 0; ai < 4; ai++)
        #pragma unroll
        for (int bj = 0; bj < 8; bj++)
            #pragma unroll
            for (int cq = 0; cq < 4; cq++) acc[ai][bj][cq] = 0.f;

    auto pf = [&](int sg, int kt) {
        char* sA = smem + sg * G_STG;
        char* sB = sA + G_ASTG;
        const uint4* ag = Abase + (size_t)kt * 512;
        const uint4* bg = Bbase + (size_t)kt * 1024;
        cp16(sA + tid * 16,         ag + tid);
        cp16(sA + (tid + 256) * 16, ag + tid + 256);
        #pragma unroll
        for (int i = 0; i < 4; i++)
            cp16(sB + (tid + i * 256) * 16, bg + tid + i * 256);
    };

    pf(0, 0); CP_COMMIT();
    pf(1, 1); CP_COMMIT();
    pf(2, 2); CP_COMMIT();

    int sg = 0;
    for (int kt = 0; kt < nkt; kt++) {
        CP_WAIT2();
        __syncthreads();

        const uint4* sA = (const uint4*)(smem + sg * G_STG);
        const uint4* sB = (const uint4*)(smem + sg * G_STG + G_ASTG);
        #pragma unroll
        for (int k2 = 0; k2 < 2; k2++) {
            uint4 af[4], bf[4];
            #pragma unroll
            for (int mi = 0; mi < 4; mi++)
                af[mi] = sA[k2 * 256 + (wm * 4 + mi) * 32 + lane];
            #pragma unroll
            for (int jq = 0; jq < 4; jq++)
                bf[jq] = sB[k2 * 512 + (wn * 4 + jq) * 32 + lane];
            #pragma unroll
            for (int mi = 0; mi < 4; mi++)
                #pragma unroll
                for (int jq = 0; jq < 4; jq++) {
                    MMAH(acc[mi][jq * 2],     af[mi], bf[jq].x, bf[jq].y);
                    MMAH(acc[mi][jq * 2 + 1], af[mi], bf[jq].z, bf[jq].w);
                }
        }

        if (kt + 3 < nkt) pf((kt + 3) & 3, kt + 3);
        CP_COMMIT();
        sg = (sg + 1) & 3;
    }
    __syncthreads();

    const int lq = lane >> 2, lr = lane & 3;
    float* sC = (float*)smem;                 // [64][260]

    for (int h = 0; h < 2; h++) {
        if (wm == h) {
            #pragma unroll
            for (int mi = 0; mi < 4; mi++)
                #pragma unroll
                for (int j = 0; j < 8; j++) {
                    const int r0 = mi * 16 + lq;
                    const int c0 = wn * 64 + j * 8 + lr * 2;
                    sC[r0 * 260 + c0]           = acc[mi][j][0];
                    sC[r0 * 260 + c0 + 1]       = acc[mi][j][1];
                    sC[(r0 + 8) * 260 + c0]     = acc[mi][j][2];
                    sC[(r0 + 8) * 260 + c0 + 1] = acc[mi][j][3];
                }
        }
        __syncthreads();

        // fused bias + LSTM; cols 0..63=i, 64..127=f, 128..191=o, 192..255=g
        #pragma unroll 4
        for (int it = 0; it < 16; it++) {
            const int idx  = it * 256 + tid;       // 0..4095
            const int row  = idx >> 6;             // 0..63
            const int hc   = idx & 63;
            const float gi = sC[row * 260 + hc]        + __ldg(bias + hc);
            const float gf = sC[row * 260 + 64 + hc]   + __ldg(bias + 64 + hc);
            const float go = sC[row * 260 + 128 + hc]  + __ldg(bias + 128 + hc);
            const float gg = sC[row * 260 + 192 + hc]  + __ldg(bias + 192 + hc);
            const size_t m  = (size_t)bm0 + h * 64 + row;
            const size_t ix = m * Hh + hc;
            const float ct = sigm(gf) * cpre[ix] + sigm(gi) * tanhf(gg);
            const float ht = sigm(go) * tanhf(ct);
            ho1[ix] = ht;
            if (ho2)  ho2[ix]  = ht;
            co[ix] = ct;
            if (hscr) hscr[ix] = ht;
        }
        __syncthreads();
    }
}

// ---------------------------------------------------------------------------
// pack kernels (fp16 fragments, round-to-nearest)
// ---------------------------------------------------------------------------
__global__ void packG_k(const float* __restrict__ G)
{
    const int idx = blockIdx.x * blockDim.x + threadIdx.x;
    if (idx >= Kc * 32 * 256 * 8 * 32) return;
    const int lane = idx & 31;
    const int g16  = (idx >> 5) & 7;
    const int kb   = (idx >> 8) & 255;
    const int mt   = (idx >> 16) & 31;
    const int zi   = idx >> 21;
    const int gg = lane >> 2, tt = lane & 3;
    const int r = mt * 128 + g16 * 16 + gg;
    const int c = kb * 16 + tt * 2;
    const float* Gz = G + (size_t)zi * Nn * Nn;
    uint4 v;
    v.x = h2pack(Gz[(size_t)r * Nn + c],           Gz[(size_t)r * Nn + c + 1]);
    v.y = h2pack(Gz[(size_t)(r + 8) * Nn + c],     Gz[(size_t)(r + 8) * Nn + c + 1]);
    v.z = h2pack(Gz[(size_t)r * Nn + c + 8],       Gz[(size_t)r * Nn + c + 9]);
    v.w = h2pack(Gz[(size_t)(r + 8) * Nn + c + 8], Gz[(size_t)(r + 8) * Nn + c + 9]);
    g_GPh[idx] = v;
}

__device__ __forceinline__ float comb0_val(const float* x, const float* h0, int m, int col) {
    const int b = col / P0, p = col - b * P0;
    return (p < Cc) ? x[((size_t)b * Nn + m) * Cc + p]
                    : h0[((size_t)b * Nn + m) * Hh + (p - Cc)];
}
__device__ __forceinline__ float comb1_val(const float* h1, int m, int col) {
    const int b = col >> 7, p = col & 127;
    return (p < Hh) ? g_ht0[((size_t)b * Nn + m) * Hh + p]
                    : h1[((size_t)b * Nn + m) * Hh + (p - Hh)];
}

__global__ void packC0_k(const float* __restrict__ x, const float* __restrict__ h0, int total)
{
    const int idx = blockIdx.x * blockDim.x + threadIdx.x;
    if (idx >= total) return;
    const int lane = idx & 31;
    const int jq   = (idx >> 5) & 15;
    const int kb   = (idx >> 9) & 255;
    const int nt   = idx >> 17;
    const int gg = lane >> 2, tt = lane & 3;
    const int na = nt * 256 + jq * 16 + gg;
    const int nb = na + 8;
    const int k0 = kb * 16 + tt * 2;
    uint4 v;
    v.x = h2pack(comb0_val(x, h0, k0,     na), comb0_val(x, h0, k0 + 1, na));
    v.y = h2pack(comb0_val(x, h0, k0 + 8, na), comb0_val(x, h0, k0 + 9, na));
    v.z = h2pack(comb0_val(x, h0, k0,     nb), comb0_val(x, h0, k0 + 1, nb));
    v.w = h2pack(comb0_val(x, h0, k0 + 8, nb), comb0_val(x, h0, k0 + 9, nb));
    g_combPh[idx] = v;
}
__global__ void packC1_k(const float* __restrict__ h1, int total)
{
    const int idx = blockIdx.x * blockDim.x + threadIdx.x;
    if (idx >= total) return;
    const int lane = idx & 31;
    const int jq   = (idx >> 5) & 15;
    const int kb   = (idx >> 9) & 255;
    const int nt   = idx >> 17;
    const int gg = lane >> 2, tt = lane & 3;
    const int na = nt * 256 + jq * 16 + gg;
    const int nb = na + 8;
    const int k0 = kb * 16 + tt * 2;
    uint4 v;
    v.x = h2pack(comb1_val(h1, k0,     na), comb1_val(h1, k0 + 1, na));
    v.y = h2pack(comb1_val(h1, k0 + 8, na), comb1_val(h1, k0 + 9, na));
    v.z = h2pack(comb1_val(h1, k0,     nb), comb1_val(h1, k0 + 1, nb));
    v.w = h2pack(comb1_val(h1, k0 + 8, nb), comb1_val(h1, k0 + 9, nb));
    g_combPh[idx] = v;
}

__global__ void packW_k(const float* __restrict__ W, int KPv, int total)
{
    const int idx = blockIdx.x * blockDim.x + threadIdx.x;
    if (idx >= total) return;
    const int lane = idx & 31;
    const int jq   = (idx >> 5) & 15;
    const int kb   = idx >> 9;
    const int gg = lane >> 2, tt = lane & 3;
    const int na = jq * 16 + gg;
    const int nb = na + 8;
    const int k0 = kb * 16 + tt * 2;
    auto wv = [&](int k, int n) -> float {
        return (k < KPv) ? W[(size_t)k * GH + n] : 0.f;
    };
    uint4 v;
    v.x = h2pack(wv(k0, na),     wv(k0 + 1, na));
    v.y = h2pack(wv(k0 + 8, na), wv(k0 + 9, na));
    v.z = h2pack(wv(k0, nb),     wv(k0 + 1, nb));
    v.w = h2pack(wv(k0 + 8, nb), wv(k0 + 9, nb));
    g_WtPh[idx] = v;
}

// ---------------------------------------------------------------------------
extern "C" void kernel_launch(void* const* d_in, const int* in_sizes, int n_in,
                              void* d_out, int out_size)
{
    (void)in_sizes; (void)n_in; (void)out_size;
    const float* G  = (const float*)d_in[0];
    const float* xt = (const float*)d_in[1];
    const float* h0 = (const float*)d_in[2];
    const float* h1 = (const float*)d_in[3];
    const float* c0 = (const float*)d_in[4];
    const float* c1 = (const float*)d_in[5];
    const float* W0 = (const float*)d_in[6];
    const float* b0 = (const float*)d_in[7];
    const float* W1 = (const float*)d_in[8];
    const float* b1 = (const float*)d_in[9];
    float* out = (float*)d_out;

    uint4 *GP, *combP, *suppP, *WtP;
    float *ht0;
    cudaGetSymbolAddress((void**)&GP,    g_GPh);
    cudaGetSymbolAddress((void**)&combP, g_combPh);
    cudaGetSymbolAddress((void**)&suppP, g_suppPh);
    cudaGetSymbolAddress((void**)&WtP,   g_WtPh);
    cudaGetSymbolAddress((void**)&ht0,   g_ht0);

    cudaFuncSetAttribute(supp128<P0>, cudaFuncAttributeMaxDynamicSharedMemorySize, S_SMEM);
    cudaFuncSetAttribute(supp128<P1>, cudaFuncAttributeMaxDynamicSharedMemorySize, S_SMEM);
    cudaFuncSetAttribute(gemm_gates,  cudaFuncAttributeMaxDynamicSharedMemorySize, G_SMEM);

    const size_t S = (size_t)ROWS * Hh;   // 8388608 per output slot
    const int nktG32  = Nn / 32;          // 128 (32-K tiles, supp GEMM)
    const int nkt0_32 = 8;                // gates layer0, K padded 240 -> 256
    const int nkt1_32 = 12;               // gates layer1, K = 384
    const int nktOut0 = 16;               // 16-K blocks in suppP (layer0)
    const int nktOut1 = 24;

    // pack G (both layers)
    packG_k<<<(Kc * 32 * 256 * 8 * 32) / 256, 256>>>(G);

    // ---- layer 0 ----
    {
        const int tot = (NC0 / 256) * 256 * 16 * 32;   // nt=10
        packC0_k<<<(tot + 255) / 256, 256>>>(xt, h0, tot);
    }
    supp128<P0><<<dim3(NC0 / 128, Nn / 128, Kc), 256, S_SMEM>>>(
        GP, combP, nktG32, suppP, nktOut0);
    {
        const int tot = nktOut0 * 16 * 32;
        packW_k<<<(tot + 255) / 256, 256>>>(W0, KP0, tot);
    }
    gemm_gates<<<dim3(1, ROWS / 128, 1), 256, G_SMEM>>>(
        suppP, WtP, nkt0_32,
        b0, c0, out + S, nullptr, out + 3 * S, ht0);

    // ---- layer 1 ----
    {
        const int tot = (NC1 / 256) * 256 * 16 * 32;   // nt=16
        packC1_k<<<(tot + 255) / 256, 256>>>(h1, tot);
    }
    supp128<P1><<<dim3(NC1 / 128, Nn / 128, Kc), 256, S_SMEM>>>(
        GP, combP, nktG32, suppP, nktOut1);
    {
        const int tot = nktOut1 * 16 * 32;
        packW_k<<<(tot + 255) / 256, 256>>>(W1, KP1, tot);
    }
    gemm_gates<<<dim3(1, ROWS / 128, 1), 256, G_SMEM>>>(
        suppP, WtP, nkt1_32,
        b1, c1, out, out + 2 * S, out + 4 * S, nullptr);
}

// round 14
// speedup vs baseline: 2.6533x; 1.0773x over previous
#include <cuda_runtime.h>
#include <cuda_fp16.h>
#include <math.h>
#include <stdint.h>

// ---------------- problem constants ----------------
#define Nn    4096
#define Bb    32
#define Cc    16
#define Hh    64
#define Kc    3
#define P0    80
#define P1    128
#define NC0   (Bb*P0)     // 2560
#define NC1   (Bb*P1)     // 4096
#define KP0   (Kc*P0)     // 240
#define KP1   (Kc*P1)     // 384
#define GH    256
#define ROWS  (Bb*Nn)     // 131072

// ---------------- GEMM tiling (fp16 operands, fp32 accum) ----------------
#define BM   128
#define BN   256
#define ASTG 8192                  // 128x32 fp16 packed A
#define BSTG 16384                 // 32x256 fp16 packed B
#define STG  (ASTG + BSTG)         // 24576
#define SMEM_MAIN (4 * STG)        // 98304

// ---------------- scratch (__device__ globals, fragment-packed fp16) -------
// A for supp GEMM: [z(3)][mt(32)][kb16(256)][g16(8)][lane(32)] uint4
__device__ uint4 g_GPh   [(size_t)Kc * 32 * 256 * 8 * 32];     // 100.7 MB
// B (comb): [nt(<=16)][kb16(256)][jq(16)][lane(32)] uint4
__device__ uint4 g_combPh[(size_t)16 * 256 * 16 * 32];         // 33.5 MB
// A for gates GEMM: [mt(1024)][kb16(<=24)][g16(8)][lane(32)] uint4
__device__ uint4 g_suppPh[(size_t)1024 * 24 * 8 * 32];         // 100.7 MB
// B (W): [kb16(<=24)][jq(16)][lane(32)] uint4
__device__ uint4 g_WtPh  [(size_t)24 * 16 * 32];
__device__ float g_ht0   [(size_t)ROWS * Hh];                  // 33.5 MB

// ---------------- helpers ----------------
__device__ __forceinline__ float sigm(float x) { return 1.f / (1.f + expf(-x)); }

__device__ __forceinline__ uint32_t h2pack(float a, float b) {
    __half2 h = __halves2half2(__float2half_rn(a), __float2half_rn(b));
    return *reinterpret_cast<uint32_t*>(&h);
}

__device__ __forceinline__ void cp16(void* s, const void* g) {
    uint32_t a;
    asm("{ .reg .u64 t; cvta.to.shared.u64 t, %1; cvt.u32.u64 %0, t; }" : "=r"(a) : "l"(s));
    asm volatile("cp.async.cg.shared.global [%0], [%1], 16;" :: "r"(a), "l"(g));
}
#define CP_COMMIT() asm volatile("cp.async.commit_group;")
#define CP_WAIT2()  asm volatile("cp.async.wait_group 2;")
#define CP_WAIT0()  asm volatile("cp.async.wait_group 0;")

// fp16 MMA: D(f32) += A(f16) * B(f16); m16n8k16
#define MMAH(accq, af, b0, b1) \
    asm volatile("mma.sync.aligned.m16n8k16.row.col.f32.f16.f16.f32 " \
        "{%0,%1,%2,%3}, {%4,%5,%6,%7}, {%8,%9}, {%0,%1,%2,%3};" \
        : "+f"((accq)[0]), "+f"((accq)[1]), "+f"((accq)[2]), "+f"((accq)[3]) \
        : "r"((af).x), "r"((af).y), "r"((af).z), "r"((af).w), "r"(b0), "r"(b1))

// ---------------------------------------------------------------------------
// Packed-fragment fp16 GEMM, SOFTWARE-PIPELINED. C[128x256] per CTA; K in
// 32-wide tiles (two 16-K fragment blocks). 8 warps (2x4), warp tile 64x64.
// Register ping-pong: frag buffers with fixed roles (buf0 = k16 step 0,
// buf1 = step 1). Every 8-LDS batch issues under an independent 32-MMA block.
// MODE 0: emit supp as packed fp16 A-fragments for the gates GEMM.
// MODE 1: fused bias + LSTM.
// nkt in 32-K tiles; nktOut (MODE 0) in 16-K blocks.
// ---------------------------------------------------------------------------
template<int MODE, int PC>
__global__ void __launch_bounds__(256, 1)
gemm_fp16(const uint4* __restrict__ Ap, const uint4* __restrict__ Bp,
          int nkt, uint4* __restrict__ outP, int nktOut,
          const float* __restrict__ bias, const float* __restrict__ cpre,
          float* __restrict__ ho1, float* __restrict__ ho2,
          float* __restrict__ co,  float* __restrict__ hscr)
{
    extern __shared__ char smem[];
    const int tid  = threadIdx.x;
    const int wid  = tid >> 5, lane = tid & 31;
    const int wm   = wid >> 2, wn = wid & 3;
    const int bm0  = blockIdx.y * BM;
    const int bn0  = blockIdx.x * BN;
    const int zz   = blockIdx.z;

    // uint4 units: A kb16 block = 256, B kb16 block = 512
    const uint4* Abase = Ap + ((size_t)zz * gridDim.y + blockIdx.y) * (size_t)(2 * nkt) * 256;
    const uint4* Bbase = Bp + (size_t)blockIdx.x * (size_t)(2 * nkt) * 512;

    float acc[4][8][4];
    #pragma unroll
    for (int ai = 0; ai < 4; ai++)
        #pragma unroll
        for (int bj = 0; bj < 8; bj++)
            #pragma unroll
            for (int cq = 0; cq < 4; cq++) acc[ai][bj][cq] = 0.f;

    auto pf = [&](int sg, int kt) {
        char* sA = smem + sg * STG;
        char* sB = sA + ASTG;
        const uint4* ag = Abase + (size_t)kt * 512;
        const uint4* bg = Bbase + (size_t)kt * 1024;
        cp16(sA + tid * 16,         ag + tid);
        cp16(sA + (tid + 256) * 16, ag + tid + 256);
        #pragma unroll
        for (int i = 0; i < 4; i++)
            cp16(sB + (tid + i * 256) * 16, bg + tid + i * 256);
    };

    pf(0, 0); CP_COMMIT();
    if (nkt > 1) pf(1, 1);
    CP_COMMIT();
    if (nkt > 2) pf(2, 2);
    CP_COMMIT();
    CP_WAIT2();
    __syncthreads();

    uint4 af0[4], bf0[4], af1[4], bf1[4];   // fixed-role frag buffers

    {   // prologue: k2=0 frags of tile 0
        const uint4* sA = (const uint4*)(smem);
        const uint4* sB = (const uint4*)(smem + ASTG);
        #pragma unroll
        for (int mi = 0; mi < 4; mi++) af0[mi] = sA[(wm * 4 + mi) * 32 + lane];
        #pragma unroll
        for (int jq = 0; jq < 4; jq++) bf0[jq] = sB[(wn * 4 + jq) * 32 + lane];
    }

    for (int kt = 0; kt < nkt; kt++) {
        const int sg = kt & 3;
        const uint4* sA = (const uint4*)(smem + sg * STG);
        const uint4* sB = (const uint4*)(smem + sg * STG + ASTG);

        // load k2=1 frags (hidden under the k2=0 MMA block below)
        #pragma unroll
        for (int mi = 0; mi < 4; mi++) af1[mi] = sA[256 + (wm * 4 + mi) * 32 + lane];
        #pragma unroll
        for (int jq = 0; jq < 4; jq++) bf1[jq] = sB[512 + (wn * 4 + jq) * 32 + lane];

        // MMAs for k2=0
        #pragma unroll
        for (int mi = 0; mi < 4; mi++)
            #pragma unroll
            for (int jq = 0; jq < 4; jq++) {
                MMAH(acc[mi][jq * 2],     af0[mi], bf0[jq].x, bf0[jq].y);
                MMAH(acc[mi][jq * 2 + 1], af0[mi], bf0[jq].z, bf0[jq].w);
            }

        if (kt + 3 < nkt) pf((kt + 3) & 3, kt + 3);
        CP_COMMIT();

        if (kt + 1 < nkt) {
            CP_WAIT2();
            __syncthreads();
            const int sg2 = (kt + 1) & 3;
            const uint4* sA2 = (const uint4*)(smem + sg2 * STG);
            const uint4* sB2 = (const uint4*)(smem + sg2 * STG + ASTG);
            // load next tile's k2=0 frags (hidden under the k2=1 MMA block)
            #pragma unroll
            for (int mi = 0; mi < 4; mi++) af0[mi] = sA2[(wm * 4 + mi) * 32 + lane];
            #pragma unroll
            for (int jq = 0; jq < 4; jq++) bf0[jq] = sB2[(wn * 4 + jq) * 32 + lane];
        }

        // MMAs for k2=1
        #pragma unroll
        for (int mi = 0; mi < 4; mi++)
            #pragma unroll
            for (int jq = 0; jq < 4; jq++) {
                MMAH(acc[mi][jq * 2],     af1[mi], bf1[jq].x, bf1[jq].y);
                MMAH(acc[mi][jq * 2 + 1], af1[mi], bf1[jq].z, bf1[jq].w);
            }
    }
    CP_WAIT0();
    __syncthreads();

    // ---------------- epilogue (staged per 64-row half) ----------------
    const int lq = lane >> 2, lr = lane & 3;
    float* sC = (float*)smem;                 // [64][260]

    for (int h = 0; h < 2; h++) {
        if (wm == h) {
            #pragma unroll
            for (int mi = 0; mi < 4; mi++)
                #pragma unroll
                for (int j = 0; j < 8; j++) {
                    const int r0 = mi * 16 + lq;
                    const int c0 = wn * 64 + j * 8 + lr * 2;
                    sC[r0 * 260 + c0]           = acc[mi][j][0];
                    sC[r0 * 260 + c0 + 1]       = acc[mi][j][1];
                    sC[(r0 + 8) * 260 + c0]     = acc[mi][j][2];
                    sC[(r0 + 8) * 260 + c0 + 1] = acc[mi][j][3];
                }
        }
        __syncthreads();

        if constexpr (MODE == 0) {
            // emit packed fp16 A-fragments for the gates GEMM
            // 2048 uint4 per half: [lkb(16)][g16h(4)][lane(32)]
            #pragma unroll 4
            for (int it = 0; it < 8; it++) {
                const int idx  = it * 256 + tid;       // 0..2047
                const int ln2  = idx & 31;
                const int g16h = (idx >> 5) & 3;
                const int lkb  = idx >> 7;             // 0..15
                const int gg = ln2 >> 2, tt = ln2 & 3;
                const int rl0 = g16h * 16 + gg;        // local row in half
                const int c0  = lkb * 16 + tt * 2;
                uint4 ha;
                ha.x = h2pack(sC[rl0 * 260 + c0],           sC[rl0 * 260 + c0 + 1]);
                ha.y = h2pack(sC[(rl0 + 8) * 260 + c0],     sC[(rl0 + 8) * 260 + c0 + 1]);
                ha.z = h2pack(sC[rl0 * 260 + c0 + 8],       sC[rl0 * 260 + c0 + 9]);
                ha.w = h2pack(sC[(rl0 + 8) * 260 + c0 + 8], sC[(rl0 + 8) * 260 + c0 + 9]);
                const int gcb  = bn0 + lkb * 16;       // 16-aligned col block
                const int bi   = gcb / PC;
                const int kidx = zz * PC + (gcb - bi * PC);
                const int kt2  = kidx >> 4;
                const int mtg  = bi * (Nn / 128) + (bm0 >> 7);
                const int g16g = h * 4 + g16h;
                const size_t f4i =
                    (((size_t)mtg * nktOut + kt2) * 8 + g16g) * 32 + ln2;
                outP[f4i] = ha;
            }
        } else {
            // fused bias + LSTM; cols 0..63=i, 64..127=f, 128..191=o, 192..255=g
            #pragma unroll 4
            for (int it = 0; it < 16; it++) {
                const int idx  = it * 256 + tid;       // 0..4095
                const int row  = idx >> 6;             // 0..63
                const int hc   = idx & 63;
                const float gi = sC[row * 260 + hc]        + __ldg(bias + hc);
                const float gf = sC[row * 260 + 64 + hc]   + __ldg(bias + 64 + hc);
                const float go = sC[row * 260 + 128 + hc]  + __ldg(bias + 128 + hc);
                const float gg = sC[row * 260 + 192 + hc]  + __ldg(bias + 192 + hc);
                const size_t m  = (size_t)bm0 + h * 64 + row;
                const size_t ix = m * Hh + hc;
                const float ct = sigm(gf) * cpre[ix] + sigm(gi) * tanhf(gg);
                const float ht = sigm(go) * tanhf(ct);
                ho1[ix] = ht;
                if (ho2)  ho2[ix]  = ht;
                co[ix] = ct;
                if (hscr) hscr[ix] = ht;
            }
        }
        __syncthreads();
    }
}

// ---------------------------------------------------------------------------
// pack kernels (fp16 fragments, round-to-nearest)
// ---------------------------------------------------------------------------
__global__ void packG_k(const float* __restrict__ G)
{
    const int idx = blockIdx.x * blockDim.x + threadIdx.x;
    if (idx >= Kc * 32 * 256 * 8 * 32) return;
    const int lane = idx & 31;
    const int g16  = (idx >> 5) & 7;
    const int kb   = (idx >> 8) & 255;
    const int mt   = (idx >> 16) & 31;
    const int zi   = idx >> 21;
    const int gg = lane >> 2, tt = lane & 3;
    const int r = mt * 128 + g16 * 16 + gg;
    const int c = kb * 16 + tt * 2;
    const float* Gz = G + (size_t)zi * Nn * Nn;
    uint4 v;
    v.x = h2pack(Gz[(size_t)r * Nn + c],           Gz[(size_t)r * Nn + c + 1]);
    v.y = h2pack(Gz[(size_t)(r + 8) * Nn + c],     Gz[(size_t)(r + 8) * Nn + c + 1]);
    v.z = h2pack(Gz[(size_t)r * Nn + c + 8],       Gz[(size_t)r * Nn + c + 9]);
    v.w = h2pack(Gz[(size_t)(r + 8) * Nn + c + 8], Gz[(size_t)(r + 8) * Nn + c + 9]);
    g_GPh[idx] = v;
}

__device__ __forceinline__ float comb0_val(const float* x, const float* h0, int m, int col) {
    const int b = col / P0, p = col - b * P0;
    return (p < Cc) ? x[((size_t)b * Nn + m) * Cc + p]
                    : h0[((size_t)b * Nn + m) * Hh + (p - Cc)];
}
__device__ __forceinline__ float comb1_val(const float* h1, int m, int col) {
    const int b = col >> 7, p = col & 127;
    return (p < Hh) ? g_ht0[((size_t)b * Nn + m) * Hh + p]
                    : h1[((size_t)b * Nn + m) * Hh + (p - Hh)];
}

__global__ void packC0_k(const float* __restrict__ x, const float* __restrict__ h0, int total)
{
    const int idx = blockIdx.x * blockDim.x + threadIdx.x;
    if (idx >= total) return;
    const int lane = idx & 31;
    const int jq   = (idx >> 5) & 15;
    const int kb   = (idx >> 9) & 255;
    const int nt   = idx >> 17;
    const int gg = lane >> 2, tt = lane & 3;
    const int na = nt * 256 + jq * 16 + gg;
    const int nb = na + 8;
    const int k0 = kb * 16 + tt * 2;
    uint4 v;
    v.x = h2pack(comb0_val(x, h0, k0,     na), comb0_val(x, h0, k0 + 1, na));
    v.y = h2pack(comb0_val(x, h0, k0 + 8, na), comb0_val(x, h0, k0 + 9, na));
    v.z = h2pack(comb0_val(x, h0, k0,     nb), comb0_val(x, h0, k0 + 1, nb));
    v.w = h2pack(comb0_val(x, h0, k0 + 8, nb), comb0_val(x, h0, k0 + 9, nb));
    g_combPh[idx] = v;
}
__global__ void packC1_k(const float* __restrict__ h1, int total)
{
    const int idx = blockIdx.x * blockDim.x + threadIdx.x;
    if (idx >= total) return;
    const int lane = idx & 31;
    const int jq   = (idx >> 5) & 15;
    const int kb   = (idx >> 9) & 255;
    const int nt   = idx >> 17;
    const int gg = lane >> 2, tt = lane & 3;
    const int na = nt * 256 + jq * 16 + gg;
    const int nb = na + 8;
    const int k0 = kb * 16 + tt * 2;
    uint4 v;
    v.x = h2pack(comb1_val(h1, k0,     na), comb1_val(h1, k0 + 1, na));
    v.y = h2pack(comb1_val(h1, k0 + 8, na), comb1_val(h1, k0 + 9, na));
    v.z = h2pack(comb1_val(h1, k0,     nb), comb1_val(h1, k0 + 1, nb));
    v.w = h2pack(comb1_val(h1, k0 + 8, nb), comb1_val(h1, k0 + 9, nb));
    g_combPh[idx] = v;
}

__global__ void packW_k(const float* __restrict__ W, int KPv, int total)
{
    const int idx = blockIdx.x * blockDim.x + threadIdx.x;
    if (idx >= total) return;
    const int lane = idx & 31;
    const int jq   = (idx >> 5) & 15;
    const int kb   = idx >> 9;
    const int gg = lane >> 2, tt = lane & 3;
    const int na = jq * 16 + gg;
    const int nb = na + 8;
    const int k0 = kb * 16 + tt * 2;
    auto wv = [&](int k, int n) -> float {
        return (k < KPv) ? W[(size_t)k * GH + n] : 0.f;
    };
    uint4 v;
    v.x = h2pack(wv(k0, na),     wv(k0 + 1, na));
    v.y = h2pack(wv(k0 + 8, na), wv(k0 + 9, na));
    v.z = h2pack(wv(k0, nb),     wv(k0 + 1, nb));
    v.w = h2pack(wv(k0 + 8, nb), wv(k0 + 9, nb));
    g_WtPh[idx] = v;
}

// ---------------------------------------------------------------------------
extern "C" void kernel_launch(void* const* d_in, const int* in_sizes, int n_in,
                              void* d_out, int out_size)
{
    (void)in_sizes; (void)n_in; (void)out_size;
    const float* G  = (const float*)d_in[0];
    const float* xt = (const float*)d_in[1];
    const float* h0 = (const float*)d_in[2];
    const float* h1 = (const float*)d_in[3];
    const float* c0 = (const float*)d_in[4];
    const float* c1 = (const float*)d_in[5];
    const float* W0 = (const float*)d_in[6];
    const float* b0 = (const float*)d_in[7];
    const float* W1 = (const float*)d_in[8];
    const float* b1 = (const float*)d_in[9];
    float* out = (float*)d_out;

    uint4 *GP, *combP, *suppP, *WtP;
    float *ht0;
    cudaGetSymbolAddress((void**)&GP,    g_GPh);
    cudaGetSymbolAddress((void**)&combP, g_combPh);
    cudaGetSymbolAddress((void**)&suppP, g_suppPh);
    cudaGetSymbolAddress((void**)&WtP,   g_WtPh);
    cudaGetSymbolAddress((void**)&ht0,   g_ht0);

    cudaFuncSetAttribute(gemm_fp16<0, P0>, cudaFuncAttributeMaxDynamicSharedMemorySize, SMEM_MAIN);
    cudaFuncSetAttribute(gemm_fp16<0, P1>, cudaFuncAttributeMaxDynamicSharedMemorySize, SMEM_MAIN);
    cudaFuncSetAttribute(gemm_fp16<1, P0>, cudaFuncAttributeMaxDynamicSharedMemorySize, SMEM_MAIN);

    const size_t S = (size_t)ROWS * Hh;   // 8388608 per output slot
    const int nktG32  = Nn / 32;          // 128 (32-K tiles, supp GEMM)
    const int nkt0_32 = 8;                // gates layer0, K padded 240 -> 256
    const int nkt1_32 = 12;               // gates layer1, K = 384
    const int nktOut0 = 16;               // 16-K blocks in suppP (layer0)
    const int nktOut1 = 24;

    // pack G (both layers)
    packG_k<<<(Kc * 32 * 256 * 8 * 32) / 256, 256>>>(G);

    // ---- layer 0 ----
    {
        const int tot = (NC0 / 256) * 256 * 16 * 32;   // nt=10
        packC0_k<<<(tot + 255) / 256, 256>>>(xt, h0, tot);
    }
    gemm_fp16<0, P0><<<dim3(NC0 / BN, Nn / BM, Kc), 256, SMEM_MAIN>>>(
        GP, combP, nktG32, suppP, nktOut0,
        nullptr, nullptr, nullptr, nullptr, nullptr, nullptr);
    {
        const int tot = nktOut0 * 16 * 32;
        packW_k<<<(tot + 255) / 256, 256>>>(W0, KP0, tot);
    }
    gemm_fp16<1, P0><<<dim3(1, ROWS / BM, 1), 256, SMEM_MAIN>>>(
        suppP, WtP, nkt0_32, nullptr, 0,
        b0, c0, out + S, nullptr, out + 3 * S, ht0);

    // ---- layer 1 ----
    {
        const int tot = (NC1 / 256) * 256 * 16 * 32;   // nt=16
        packC1_k<<<(tot + 255) / 256, 256>>>(h1, tot);
    }
    gemm_fp16<0, P1><<<dim3(NC1 / BN, Nn / BM, Kc), 256, SMEM_MAIN>>>(
        GP, combP, nktG32, suppP, nktOut1,
        nullptr, nullptr, nullptr, nullptr, nullptr, nullptr);
    {
        const int tot = nktOut1 * 16 * 32;
        packW_k<<<(tot + 255) / 256, 256>>>(W1, KP1, tot);
    }
    gemm_fp16<1, P0><<<dim3(1, ROWS / BM, 1), 256, SMEM_MAIN>>>(
        suppP, WtP, nkt1_32, nullptr, 0,
        b1, c1, out, out + 2 * S, out + 4 * S, nullptr);
}